// round 9
// baseline (speedup 1.0000x reference)
#include <cuda_runtime.h>
#include <cuda_bf16.h>
#include <stdint.h>
#include <math.h>

// Problem constants (fixed): B=2, S=2048, D=2048, H=16
#define BATCH  2
#define SEQ    2048
#define DMODEL 2048
#define NHEAD  16
#define HDIM   128
#define MROWS  (BATCH * SEQ)   // 4096

// ================= scratch (device globals: allocation-free) =================
__device__ __nv_bfloat16 g_qhi [(size_t)MROWS * DMODEL];
__device__ __nv_bfloat16 g_qlo [(size_t)MROWS * DMODEL];
__device__ __nv_bfloat16 g_khi [(size_t)MROWS * DMODEL];
__device__ __nv_bfloat16 g_klo [(size_t)MROWS * DMODEL];
__device__ __nv_bfloat16 g_vhi [(size_t)MROWS * DMODEL];
__device__ __nv_bfloat16 g_vlo [(size_t)MROWS * DMODEL];
__device__ __nv_bfloat16 g_aohi[(size_t)MROWS * DMODEL];
__device__ __nv_bfloat16 g_aolo[(size_t)MROWS * DMODEL];

__device__ __nv_bfloat16 g_xhi [(size_t)MROWS * DMODEL];
__device__ __nv_bfloat16 g_xlo [(size_t)MROWS * DMODEL];
__device__ __nv_bfloat16 g_wqhi[(size_t)DMODEL * DMODEL];
__device__ __nv_bfloat16 g_wqlo[(size_t)DMODEL * DMODEL];
__device__ __nv_bfloat16 g_wkhi[(size_t)DMODEL * DMODEL];
__device__ __nv_bfloat16 g_wklo[(size_t)DMODEL * DMODEL];
__device__ __nv_bfloat16 g_wvhi[(size_t)DMODEL * DMODEL];
__device__ __nv_bfloat16 g_wvlo[(size_t)DMODEL * DMODEL];
__device__ __nv_bfloat16 g_wphi[(size_t)DMODEL * DMODEL];
__device__ __nv_bfloat16 g_wplo[(size_t)DMODEL * DMODEL];

// ================= PTX helpers (baseline features only) ======
__device__ __forceinline__ uint32_t smem_u32(const void* p) {
    uint32_t a;
    asm("{ .reg .u64 t; cvta.to.shared.u64 t, %1; cvt.u32.u64 %0, t; }" : "=r"(a) : "l"(p));
    return a;
}
__device__ __forceinline__ void cp_async16(uint32_t dst, const void* src) {
    asm volatile("cp.async.cg.shared.global [%0], [%1], 16;" :: "r"(dst), "l"(src) : "memory");
}
__device__ __forceinline__ void cp_commit() {
    asm volatile("cp.async.commit_group;" ::: "memory");
}
__device__ __forceinline__ void cp_wait1() {
    asm volatile("cp.async.wait_group 1;" ::: "memory");
}
__device__ __forceinline__ void cp_wait0() {
    asm volatile("cp.async.wait_group 0;" ::: "memory");
}
__device__ __forceinline__ void ldm_x4(uint32_t& r0, uint32_t& r1, uint32_t& r2, uint32_t& r3,
                                       uint32_t addr) {
    asm volatile("ldmatrix.sync.aligned.m8n8.x4.shared.b16 {%0,%1,%2,%3}, [%4];"
                 : "=r"(r0), "=r"(r1), "=r"(r2), "=r"(r3) : "r"(addr));
}
__device__ __forceinline__ void ldm_x4_t(uint32_t& r0, uint32_t& r1, uint32_t& r2, uint32_t& r3,
                                         uint32_t addr) {
    asm volatile("ldmatrix.sync.aligned.m8n8.x4.trans.shared.b16 {%0,%1,%2,%3}, [%4];"
                 : "=r"(r0), "=r"(r1), "=r"(r2), "=r"(r3) : "r"(addr));
}
__device__ __forceinline__ void mma_bf16(float* c, const uint32_t* a, const uint32_t* b) {
    asm volatile("mma.sync.aligned.m16n8k16.row.col.f32.bf16.bf16.f32 "
                 "{%0,%1,%2,%3}, {%4,%5,%6,%7}, {%8,%9}, {%0,%1,%2,%3};"
                 : "+f"(c[0]), "+f"(c[1]), "+f"(c[2]), "+f"(c[3])
                 : "r"(a[0]), "r"(a[1]), "r"(a[2]), "r"(a[3]), "r"(b[0]), "r"(b[1]));
}
__device__ __forceinline__ void mma_bf16_2(float* c, const uint32_t* a, uint32_t b0, uint32_t b1) {
    asm volatile("mma.sync.aligned.m16n8k16.row.col.f32.bf16.bf16.f32 "
                 "{%0,%1,%2,%3}, {%4,%5,%6,%7}, {%8,%9}, {%0,%1,%2,%3};"
                 : "+f"(c[0]), "+f"(c[1]), "+f"(c[2]), "+f"(c[3])
                 : "r"(a[0]), "r"(a[1]), "r"(a[2]), "r"(a[3]), "r"(b0), "r"(b1));
}
// pack two fp32 into bf16x2: low half = f0, high half = f1
__device__ __forceinline__ uint32_t pack_bf16x2(float f0, float f1) {
    uint32_t r;
    asm("cvt.rn.bf16x2.f32 %0, %1, %2;" : "=r"(r) : "f"(f1), "f"(f0));
    return r;
}
__device__ __forceinline__ float bf16rt(float x) {
    return __bfloat162float(__float2bfloat16(x));
}

// ================= split kernels: fp32 -> (hi, lo) bf16 =================
__device__ __forceinline__ void split_one(const float* __restrict__ src,
                                          __nv_bfloat16* __restrict__ hi,
                                          __nv_bfloat16* __restrict__ lo, int i)
{
    float4 v = ((const float4*)src)[i];
    __nv_bfloat16 h0 = __float2bfloat16(v.x), h1 = __float2bfloat16(v.y);
    __nv_bfloat16 h2 = __float2bfloat16(v.z), h3 = __float2bfloat16(v.w);
    __nv_bfloat16 l0 = __float2bfloat16(v.x - __bfloat162float(h0));
    __nv_bfloat16 l1 = __float2bfloat16(v.y - __bfloat162float(h1));
    __nv_bfloat16 l2 = __float2bfloat16(v.z - __bfloat162float(h2));
    __nv_bfloat16 l3 = __float2bfloat16(v.w - __bfloat162float(h3));
    __nv_bfloat162* hp = (__nv_bfloat162*)hi;
    __nv_bfloat162* lp = (__nv_bfloat162*)lo;
    hp[i * 2 + 0] = __nv_bfloat162(h0, h1);
    hp[i * 2 + 1] = __nv_bfloat162(h2, h3);
    lp[i * 2 + 0] = __nv_bfloat162(l0, l1);
    lp[i * 2 + 1] = __nv_bfloat162(l2, l3);
}

__global__ __launch_bounds__(256) void split_kernel(
    const float* __restrict__ src, __nv_bfloat16* __restrict__ hi,
    __nv_bfloat16* __restrict__ lo, int n4)
{
    int i = blockIdx.x * blockDim.x + threadIdx.x;
    if (i >= n4) return;
    split_one(src, hi, lo, i);
}

struct SplitSet {
    const float* src[4];
    __nv_bfloat16* hi[4];
    __nv_bfloat16* lo[4];
};
__global__ __launch_bounds__(256) void split4_kernel(SplitSet s, int n4)
{
    int i = blockIdx.x * blockDim.x + threadIdx.x;
    if (i >= n4) return;
    int t = blockIdx.y;
    split_one(s.src[t], s.hi[t], s.lo[t], i);
}

// ================= mma.sync GEMM core (CTA tile 128x128, BK=64) ==================
#define GBK        64
#define TILE_B     (128 * 128)
#define STAGE_B    (4 * TILE_B)
#define GEMM_SMEM  (2 * STAGE_B)

#define T_AHI 0
#define T_ALO (1 * TILE_B)
#define T_BHI (2 * TILE_B)
#define T_BLO (3 * TILE_B)

template<int MODE>
__device__ __forceinline__ void gemm_tile_body(
    const __nv_bfloat16* __restrict__ Ahi, const __nv_bfloat16* __restrict__ Alo,
    const __nv_bfloat16* __restrict__ Bhi, const __nv_bfloat16* __restrict__ Blo,
    float* __restrict__ C, __nv_bfloat16* __restrict__ Chi,
    __nv_bfloat16* __restrict__ Clo, float mul, int M, int N, int K,
    int m0, int n0, char* smem)
{
    const uint32_t sb = smem_u32(smem);
    const int tid = threadIdx.x;
    const int wid = tid >> 5;
    const int l   = tid & 31;
    const int wm  = wid & 3;
    const int wn  = wid >> 2;

    int lrow[4], ldst[4];
    #pragma unroll
    for (int i = 0; i < 4; i++) {
        int idx = tid + i * 256;
        int row = idx >> 3, c16 = idx & 7;
        lrow[i] = row;
        ldst[i] = row * 128 + ((c16 ^ (row & 7)) << 4);
    }

    auto issue_stage = [&](int c, int buf) {
        uint32_t s0 = sb + buf * STAGE_B;
        #pragma unroll
        for (int i = 0; i < 4; i++) {
            int row = lrow[i];
            int koff = c * GBK + ((tid + i * 256) & 7) * 8;
            cp_async16(s0 + T_AHI + ldst[i], Ahi + (size_t)(m0 + row) * K + koff);
            cp_async16(s0 + T_ALO + ldst[i], Alo + (size_t)(m0 + row) * K + koff);
            cp_async16(s0 + T_BHI + ldst[i], Bhi + (size_t)(n0 + row) * K + koff);
            cp_async16(s0 + T_BLO + ldst[i], Blo + (size_t)(n0 + row) * K + koff);
        }
        cp_commit();
    };

    const int a_rowoff = (l & 15);
    const int a_c16off = (l >> 4);
    const int b_rowoff = (l & 7) | ((l & 16) >> 1);
    const int b_c16off = (l >> 3) & 1;

    float acc[2][8][4];
    #pragma unroll
    for (int mi = 0; mi < 2; mi++)
        #pragma unroll
        for (int nj = 0; nj < 8; nj++)
            #pragma unroll
            for (int t = 0; t < 4; t++) acc[mi][nj][t] = 0.f;

    const int nchunks = K / GBK;
    issue_stage(0, 0);
    issue_stage(1, 1);

    for (int c = 0; c < nchunks; c++) {
        const int buf = c & 1;
        if (c < nchunks - 2) cp_wait1(); else cp_wait0();
        __syncthreads();

        const uint32_t s0 = sb + buf * STAGE_B;
        #pragma unroll
        for (int kk = 0; kk < 4; kk++) {
            uint32_t ahi[2][4], alo[2][4];
            #pragma unroll
            for (int mi = 0; mi < 2; mi++) {
                int row = wm * 32 + mi * 16 + a_rowoff;
                int c16 = kk * 2 + a_c16off;
                uint32_t ad = s0 + row * 128 + ((c16 ^ (row & 7)) << 4);
                ldm_x4(ahi[mi][0], ahi[mi][1], ahi[mi][2], ahi[mi][3], ad + T_AHI);
                ldm_x4(alo[mi][0], alo[mi][1], alo[mi][2], alo[mi][3], ad + T_ALO);
            }
            uint32_t bhi[8][2], blo[8][2];
            #pragma unroll
            for (int p = 0; p < 4; p++) {
                int row = wn * 64 + p * 16 + b_rowoff;
                int c16 = kk * 2 + b_c16off;
                uint32_t ad = s0 + row * 128 + ((c16 ^ (row & 7)) << 4);
                ldm_x4(bhi[2*p][0], bhi[2*p][1], bhi[2*p+1][0], bhi[2*p+1][1], ad + T_BHI);
                ldm_x4(blo[2*p][0], blo[2*p][1], blo[2*p+1][0], blo[2*p+1][1], ad + T_BLO);
            }
            #pragma unroll
            for (int mi = 0; mi < 2; mi++)
                #pragma unroll
                for (int nj = 0; nj < 8; nj++) {
                    mma_bf16(acc[mi][nj], ahi[mi], bhi[nj]);
                    mma_bf16(acc[mi][nj], ahi[mi], blo[nj]);
                    mma_bf16(acc[mi][nj], alo[mi], bhi[nj]);
                }
        }
        __syncthreads();
        if (c + 2 < nchunks) issue_stage(c + 2, buf);
    }

    const int er = l >> 2;
    const int ec = (l & 3) * 2;
    #pragma unroll
    for (int mi = 0; mi < 2; mi++) {
        int grow = m0 + wm * 32 + mi * 16 + er;
        #pragma unroll
        for (int nj = 0; nj < 8; nj++) {
            int gcol = n0 + wn * 64 + nj * 8 + ec;
            if (MODE == 0) {
                *(float2*)&C[(size_t)grow * N + gcol] =
                    make_float2(acc[mi][nj][0], acc[mi][nj][1]);
                *(float2*)&C[(size_t)(grow + 8) * N + gcol] =
                    make_float2(acc[mi][nj][2], acc[mi][nj][3]);
            } else {
                float c0 = acc[mi][nj][0] * mul, c1 = acc[mi][nj][1] * mul;
                float c2 = acc[mi][nj][2] * mul, c3 = acc[mi][nj][3] * mul;
                *(uint32_t*)&Chi[(size_t)grow * N + gcol]       = pack_bf16x2(c0, c1);
                *(uint32_t*)&Clo[(size_t)grow * N + gcol]       =
                    pack_bf16x2(c0 - bf16rt(c0), c1 - bf16rt(c1));
                *(uint32_t*)&Chi[(size_t)(grow + 8) * N + gcol] = pack_bf16x2(c2, c3);
                *(uint32_t*)&Clo[(size_t)(grow + 8) * N + gcol] =
                    pack_bf16x2(c2 - bf16rt(c2), c3 - bf16rt(c3));
            }
        }
    }
}

__global__ __launch_bounds__(256) void gemm_f32out_kernel(
    const __nv_bfloat16* __restrict__ Ahi, const __nv_bfloat16* __restrict__ Alo,
    const __nv_bfloat16* __restrict__ Bhi, const __nv_bfloat16* __restrict__ Blo,
    float* __restrict__ C, int M, int N, int K)
{
    extern __shared__ char smem[];
    gemm_tile_body<0>(Ahi, Alo, Bhi, Blo, C, nullptr, nullptr, 1.0f,
                      M, N, K, blockIdx.y * 128, blockIdx.x * 128, smem);
}

struct QKVSet {
    const __nv_bfloat16* bhi[3];
    const __nv_bfloat16* blo[3];
    __nv_bfloat16* chi[3];
    __nv_bfloat16* clo[3];
    float mul[3];
};
__global__ __launch_bounds__(256) void gemm_qkv_kernel(
    const __nv_bfloat16* __restrict__ Ahi, const __nv_bfloat16* __restrict__ Alo,
    QKVSet s, int M, int N, int K)
{
    extern __shared__ char smem[];
    const int z = blockIdx.z;
    gemm_tile_body<1>(Ahi, Alo, s.bhi[z], s.blo[z], nullptr, s.chi[z], s.clo[z],
                      s.mul[z], M, N, K, blockIdx.y * 128, blockIdx.x * 128, smem);
}

// ============================================================
// Tensor-core flash attention v2 (causal) — bf16 hi/lo inputs.
// Block: 256 threads (8 warps); BQ=128, BKV=64, hd=128.
// Warp w owns q-rows [w*16, w*16+16). Double-buffered KV stages with
// cp.async prefetch; warp-level skip of fully-masked diagonal tiles.
// smem: Q (2x32KB) + 2 stages x (4 tiles x 16KB) = 192 KB.
// ============================================================
#define FT_QHI   0
#define FT_QLO   32768
#define FT_STAGE 65536           // stage s at FT_STAGE + s*65536
#define FS_KHI   0
#define FS_KLO   16384
#define FS_VHI   32768
#define FS_VLO   49152
#define FLASH_TC_SMEM 196608

__device__ __forceinline__ uint32_t fsw(int row, int c16) {
    return (uint32_t)(row * 256 + ((c16 ^ ((row & 7) << 1)) << 4));
}

__global__ __launch_bounds__(256) void flash_attn_tc_kernel(
    const __nv_bfloat16* __restrict__ qhi, const __nv_bfloat16* __restrict__ qlo,
    const __nv_bfloat16* __restrict__ khi, const __nv_bfloat16* __restrict__ klo,
    const __nv_bfloat16* __restrict__ vhi, const __nv_bfloat16* __restrict__ vlo,
    __nv_bfloat16* __restrict__ ohi, __nv_bfloat16* __restrict__ olo)
{
    extern __shared__ char fsm[];
    const uint32_t sb = smem_u32(fsm);
    const int tid = threadIdx.x;
    const int wid = tid >> 5;
    const int l   = tid & 31;
    const int qt = gridDim.x - 1 - blockIdx.x;   // longest-first scheduling
    const int h  = blockIdx.y;
    const int b  = blockIdx.z;
    const int q0 = qt * 128;

    // ---- load Q tile (128x128 hi/lo): group 0 ----
    const size_t gq = ((size_t)b * SEQ + q0) * DMODEL + h * HDIM;
    #pragma unroll
    for (int i = 0; i < 8; i++) {
        int idx = tid + i * 256;
        int row = idx >> 4, c16 = idx & 15;
        uint32_t off = fsw(row, c16);
        size_t src = gq + (size_t)row * DMODEL + c16 * 8;
        cp_async16(sb + FT_QHI + off, qhi + src);
        cp_async16(sb + FT_QLO + off, qlo + src);
    }
    cp_commit();

    // KV stage loader: stage buffer sidx, kv tile kt
    auto issue_kv = [&](int kt, int sidx) {
        uint32_t s0 = sb + FT_STAGE + sidx * 65536;
        const size_t gkv = ((size_t)b * SEQ + kt * 64) * DMODEL + h * HDIM;
        #pragma unroll
        for (int i = 0; i < 4; i++) {
            int idx = tid + i * 256;
            int row = idx >> 4, c16 = idx & 15;
            uint32_t off = fsw(row, c16);
            size_t src = gkv + (size_t)row * DMODEL + c16 * 8;
            cp_async16(s0 + FS_KHI + off, khi + src);
            cp_async16(s0 + FS_KLO + off, klo + src);
            cp_async16(s0 + FS_VHI + off, vhi + src);
            cp_async16(s0 + FS_VLO + off, vlo + src);
        }
        cp_commit();
    };

    const int r  = l >> 2;
    const int cq = l & 3;
    const int a_rowoff = (l & 15);
    const int a_c16off = (l >> 4);
    const int b_rowoff = (l & 7) | ((l & 16) >> 1);
    const int b_c16off = (l >> 3) & 1;
    const int wrow0 = q0 + wid * 16;     // first global q-row owned by this warp

    float m0v = -1e30f, m1v = -1e30f, l0v = 0.f, l1v = 0.f;
    float O[16][4];
    #pragma unroll
    for (int g = 0; g < 16; g++)
        #pragma unroll
        for (int t = 0; t < 4; t++) O[g][t] = 0.f;

    const int nkt = 2 * qt + 2;          // kv tiles 0 .. 2qt+1
    issue_kv(0, 0);

    for (int kt = 0; kt < nkt; kt++) {
        const int sidx = kt & 1;
        if (kt + 1 < nkt) issue_kv(kt + 1, sidx ^ 1);
        if (kt + 1 < nkt) cp_wait1(); else cp_wait0();
        __syncthreads();

        const int col0 = kt * 64;
        // warp-level skip: tile entirely above this warp's causal boundary
        if (col0 <= wrow0 + 15) {
            const uint32_t s0 = sb + FT_STAGE + sidx * 65536;

            // ---- scores S = Q @ K^T (3-term bf16) ----
            float s[8][4];
            #pragma unroll
            for (int nj = 0; nj < 8; nj++)
                #pragma unroll
                for (int t = 0; t < 4; t++) s[nj][t] = 0.f;

            #pragma unroll
            for (int j = 0; j < 8; j++) {
                int arow = wid * 16 + a_rowoff;
                uint32_t aad = sb + fsw(arow, 2 * j + a_c16off);
                uint32_t ah[4], al_[4];
                ldm_x4(ah[0], ah[1], ah[2], ah[3], aad + FT_QHI);
                ldm_x4(al_[0], al_[1], al_[2], al_[3], aad + FT_QLO);

                uint32_t bh[8][2], bl[8][2];
                #pragma unroll
                for (int p = 0; p < 4; p++) {
                    int brow = p * 16 + b_rowoff;
                    uint32_t bad = s0 + fsw(brow, 2 * j + b_c16off);
                    ldm_x4(bh[2*p][0], bh[2*p][1], bh[2*p+1][0], bh[2*p+1][1], bad + FS_KHI);
                    ldm_x4(bl[2*p][0], bl[2*p][1], bl[2*p+1][0], bl[2*p+1][1], bad + FS_KLO);
                }
                #pragma unroll
                for (int nj = 0; nj < 8; nj++) {
                    mma_bf16(s[nj], ah,  bh[nj]);
                    mma_bf16(s[nj], ah,  bl[nj]);
                    mma_bf16(s[nj], al_, bh[nj]);
                }
            }

            // ---- causal mask (partial tiles only) ----
            if (col0 + 63 > wrow0) {
                #pragma unroll
                for (int nj = 0; nj < 8; nj++)
                    #pragma unroll
                    for (int t = 0; t < 4; t++) {
                        int coll = col0 + nj * 8 + 2 * cq + (t & 1);
                        int rowl = wrow0 + r + ((t >> 1) << 3);
                        if (coll > rowl) s[nj][t] = -1e30f;
                    }
            }

            // ---- online softmax (warp-private rows) ----
            float mx0 = -1e30f, mx1 = -1e30f;
            #pragma unroll
            for (int nj = 0; nj < 8; nj++) {
                mx0 = fmaxf(mx0, fmaxf(s[nj][0], s[nj][1]));
                mx1 = fmaxf(mx1, fmaxf(s[nj][2], s[nj][3]));
            }
            mx0 = fmaxf(mx0, __shfl_xor_sync(0xffffffffu, mx0, 1));
            mx0 = fmaxf(mx0, __shfl_xor_sync(0xffffffffu, mx0, 2));
            mx1 = fmaxf(mx1, __shfl_xor_sync(0xffffffffu, mx1, 1));
            mx1 = fmaxf(mx1, __shfl_xor_sync(0xffffffffu, mx1, 2));

            float mn0 = fmaxf(m0v, mx0), mn1 = fmaxf(m1v, mx1);
            float al0 = __expf(m0v - mn0), al1 = __expf(m1v - mn1);
            m0v = mn0; m1v = mn1;

            #pragma unroll
            for (int g = 0; g < 16; g++) {
                O[g][0] *= al0; O[g][1] *= al0;
                O[g][2] *= al1; O[g][3] *= al1;
            }

            float rs0 = 0.f, rs1 = 0.f;
            #pragma unroll
            for (int nj = 0; nj < 8; nj++) {
                s[nj][0] = __expf(s[nj][0] - mn0);
                s[nj][1] = __expf(s[nj][1] - mn0);
                s[nj][2] = __expf(s[nj][2] - mn1);
                s[nj][3] = __expf(s[nj][3] - mn1);
                rs0 += s[nj][0] + s[nj][1];
                rs1 += s[nj][2] + s[nj][3];
            }
            rs0 += __shfl_xor_sync(0xffffffffu, rs0, 1);
            rs0 += __shfl_xor_sync(0xffffffffu, rs0, 2);
            rs1 += __shfl_xor_sync(0xffffffffu, rs1, 1);
            rs1 += __shfl_xor_sync(0xffffffffu, rs1, 2);
            l0v = l0v * al0 + rs0;
            l1v = l1v * al1 + rs1;

            // ---- O += P @ V (3-term bf16) ----
            #pragma unroll
            for (int j = 0; j < 4; j++) {
                uint32_t pah[4], pal[4];
                {
                    float p00 = s[2*j][0],   p01 = s[2*j][1];
                    float p02 = s[2*j][2],   p03 = s[2*j][3];
                    float p10 = s[2*j+1][0], p11 = s[2*j+1][1];
                    float p12 = s[2*j+1][2], p13 = s[2*j+1][3];
                    pah[0] = pack_bf16x2(p00, p01);
                    pah[1] = pack_bf16x2(p02, p03);
                    pah[2] = pack_bf16x2(p10, p11);
                    pah[3] = pack_bf16x2(p12, p13);
                    pal[0] = pack_bf16x2(p00 - bf16rt(p00), p01 - bf16rt(p01));
                    pal[1] = pack_bf16x2(p02 - bf16rt(p02), p03 - bf16rt(p03));
                    pal[2] = pack_bf16x2(p10 - bf16rt(p10), p11 - bf16rt(p11));
                    pal[3] = pack_bf16x2(p12 - bf16rt(p12), p13 - bf16rt(p13));
                }
                #pragma unroll
                for (int g = 0; g < 8; g++) {
                    int vrow = j * 16 + (l & 15);
                    uint32_t vad = s0 + fsw(vrow, 2 * g + (l >> 4));
                    uint32_t vh0, vh1, vh2, vh3, vl0, vl1, vl2, vl3;
                    ldm_x4_t(vh0, vh1, vh2, vh3, vad + FS_VHI);
                    ldm_x4_t(vl0, vl1, vl2, vl3, vad + FS_VLO);
                    mma_bf16_2(O[2*g],     pah, vh0, vh1);
                    mma_bf16_2(O[2*g],     pah, vl0, vl1);
                    mma_bf16_2(O[2*g],     pal, vh0, vh1);
                    mma_bf16_2(O[2*g + 1], pah, vh2, vh3);
                    mma_bf16_2(O[2*g + 1], pah, vl2, vl3);
                    mma_bf16_2(O[2*g + 1], pal, vh2, vh3);
                }
            }
        }
        __syncthreads();   // release stage buffer for the next prefetch
    }

    // ---- epilogue: divide by l, write hi/lo bf16 ----
    const float i0 = 1.0f / l0v;
    const float i1 = 1.0f / l1v;
    const size_t obase = ((size_t)b * SEQ + q0 + wid * 16 + r) * DMODEL + h * HDIM;
    #pragma unroll
    for (int g = 0; g < 16; g++) {
        int col = g * 8 + 2 * cq;
        float a0 = O[g][0] * i0, a1 = O[g][1] * i0;
        float a2 = O[g][2] * i1, a3 = O[g][3] * i1;
        *(uint32_t*)&ohi[obase + col] = pack_bf16x2(a0, a1);
        *(uint32_t*)&olo[obase + col] = pack_bf16x2(a0 - bf16rt(a0), a1 - bf16rt(a1));
        *(uint32_t*)&ohi[obase + (size_t)8 * DMODEL + col] = pack_bf16x2(a2, a3);
        *(uint32_t*)&olo[obase + (size_t)8 * DMODEL + col] =
            pack_bf16x2(a2 - bf16rt(a2), a3 - bf16rt(a3));
    }
}

// ============================================================
// launcher
// ============================================================
extern "C" void kernel_launch(void* const* d_in, const int* in_sizes, int n_in,
                              void* d_out, int out_size)
{
    const float* x  = (const float*)d_in[0];
    const float* Wq = (const float*)d_in[1];
    const float* Wk = (const float*)d_in[2];
    const float* Wv = (const float*)d_in[3];
    const float* Wp = (const float*)d_in[4];
    float* out = (float*)d_out;

    void *qhi, *qlo, *khi, *klo, *vhi, *vlo, *aohi, *aolo;
    cudaGetSymbolAddress(&qhi,  g_qhi);  cudaGetSymbolAddress(&qlo,  g_qlo);
    cudaGetSymbolAddress(&khi,  g_khi);  cudaGetSymbolAddress(&klo,  g_klo);
    cudaGetSymbolAddress(&vhi,  g_vhi);  cudaGetSymbolAddress(&vlo,  g_vlo);
    cudaGetSymbolAddress(&aohi, g_aohi); cudaGetSymbolAddress(&aolo, g_aolo);

    void *xhi, *xlo;
    void *wqhi, *wqlo, *wkhi, *wklo, *wvhi, *wvlo, *wphi, *wplo;
    cudaGetSymbolAddress(&xhi,  g_xhi);  cudaGetSymbolAddress(&xlo,  g_xlo);
    cudaGetSymbolAddress(&wqhi, g_wqhi); cudaGetSymbolAddress(&wqlo, g_wqlo);
    cudaGetSymbolAddress(&wkhi, g_wkhi); cudaGetSymbolAddress(&wklo, g_wklo);
    cudaGetSymbolAddress(&wvhi, g_wvhi); cudaGetSymbolAddress(&wvlo, g_wvlo);
    cudaGetSymbolAddress(&wphi, g_wphi); cudaGetSymbolAddress(&wplo, g_wplo);

    cudaFuncSetAttribute(flash_attn_tc_kernel,
                         cudaFuncAttributeMaxDynamicSharedMemorySize, FLASH_TC_SMEM);
    cudaFuncSetAttribute(gemm_f32out_kernel,
                         cudaFuncAttributeMaxDynamicSharedMemorySize, GEMM_SMEM);
    cudaFuncSetAttribute(gemm_qkv_kernel,
                         cudaFuncAttributeMaxDynamicSharedMemorySize, GEMM_SMEM);

    const int nx4 = (MROWS * DMODEL) / 4;
    const int nw4 = (DMODEL * DMODEL) / 4;

    split_kernel<<<(nx4 + 255) / 256, 256>>>(x, (__nv_bfloat16*)xhi, (__nv_bfloat16*)xlo, nx4);
    {
        SplitSet ss;
        ss.src[0] = Wq; ss.hi[0] = (__nv_bfloat16*)wqhi; ss.lo[0] = (__nv_bfloat16*)wqlo;
        ss.src[1] = Wk; ss.hi[1] = (__nv_bfloat16*)wkhi; ss.lo[1] = (__nv_bfloat16*)wklo;
        ss.src[2] = Wv; ss.hi[2] = (__nv_bfloat16*)wvhi; ss.lo[2] = (__nv_bfloat16*)wvlo;
        ss.src[3] = Wp; ss.hi[3] = (__nv_bfloat16*)wphi; ss.lo[3] = (__nv_bfloat16*)wplo;
        dim3 sg((nw4 + 255) / 256, 4);
        split4_kernel<<<sg, 256>>>(ss, nw4);
    }

    const float scale = 0.08838834764831845f;  // 1/sqrt(128), folded into Q

    {
        QKVSet qs;
        qs.bhi[0] = (const __nv_bfloat16*)wqhi; qs.blo[0] = (const __nv_bfloat16*)wqlo;
        qs.chi[0] = (__nv_bfloat16*)qhi;        qs.clo[0] = (__nv_bfloat16*)qlo;
        qs.mul[0] = scale;
        qs.bhi[1] = (const __nv_bfloat16*)wkhi; qs.blo[1] = (const __nv_bfloat16*)wklo;
        qs.chi[1] = (__nv_bfloat16*)khi;        qs.clo[1] = (__nv_bfloat16*)klo;
        qs.mul[1] = 1.0f;
        qs.bhi[2] = (const __nv_bfloat16*)wvhi; qs.blo[2] = (const __nv_bfloat16*)wvlo;
        qs.chi[2] = (__nv_bfloat16*)vhi;        qs.clo[2] = (__nv_bfloat16*)vlo;
        qs.mul[2] = 1.0f;
        dim3 qg(DMODEL / 128, MROWS / 128, 3);   // (16, 32, 3)
        gemm_qkv_kernel<<<qg, 256, GEMM_SMEM>>>(
            (const __nv_bfloat16*)xhi, (const __nv_bfloat16*)xlo,
            qs, MROWS, DMODEL, DMODEL);
    }

    dim3 fgrid(SEQ / 128, NHEAD, BATCH);     // (16, 16, 2)
    flash_attn_tc_kernel<<<fgrid, 256, FLASH_TC_SMEM>>>(
        (const __nv_bfloat16*)qhi, (const __nv_bfloat16*)qlo,
        (const __nv_bfloat16*)khi, (const __nv_bfloat16*)klo,
        (const __nv_bfloat16*)vhi, (const __nv_bfloat16*)vlo,
        (__nv_bfloat16*)aohi, (__nv_bfloat16*)aolo);

    dim3 ggrid(DMODEL / 128, MROWS / 128);   // (16, 32)
    gemm_f32out_kernel<<<ggrid, 256, GEMM_SMEM>>>(
        (const __nv_bfloat16*)aohi, (const __nv_bfloat16*)aolo,
        (const __nv_bfloat16*)wphi, (const __nv_bfloat16*)wplo,
        out, MROWS, DMODEL, DMODEL);
}

// round 10
// speedup vs baseline: 1.1639x; 1.1639x over previous
#include <cuda_runtime.h>
#include <cuda_bf16.h>
#include <cuda_fp16.h>
#include <stdint.h>
#include <math.h>

// Problem constants (fixed): B=2, S=2048, D=2048, H=16
#define BATCH  2
#define SEQ    2048
#define DMODEL 2048
#define NHEAD  16
#define HDIM   128
#define MROWS  (BATCH * SEQ)   // 4096

// ================= scratch (device globals: allocation-free) =================
__device__ __half g_qh[(size_t)MROWS * DMODEL];
__device__ __half g_kh[(size_t)MROWS * DMODEL];
__device__ __half g_vh[(size_t)MROWS * DMODEL];
__device__ __nv_bfloat16 g_aohi[(size_t)MROWS * DMODEL];
__device__ __nv_bfloat16 g_aolo[(size_t)MROWS * DMODEL];

__device__ __nv_bfloat16 g_xhi [(size_t)MROWS * DMODEL];
__device__ __nv_bfloat16 g_xlo [(size_t)MROWS * DMODEL];
__device__ __nv_bfloat16 g_wqhi[(size_t)DMODEL * DMODEL];
__device__ __nv_bfloat16 g_wqlo[(size_t)DMODEL * DMODEL];
__device__ __nv_bfloat16 g_wkhi[(size_t)DMODEL * DMODEL];
__device__ __nv_bfloat16 g_wklo[(size_t)DMODEL * DMODEL];
__device__ __nv_bfloat16 g_wvhi[(size_t)DMODEL * DMODEL];
__device__ __nv_bfloat16 g_wvlo[(size_t)DMODEL * DMODEL];
__device__ __nv_bfloat16 g_wphi[(size_t)DMODEL * DMODEL];
__device__ __nv_bfloat16 g_wplo[(size_t)DMODEL * DMODEL];

// ================= PTX helpers (baseline features only) ======
__device__ __forceinline__ uint32_t smem_u32(const void* p) {
    uint32_t a;
    asm("{ .reg .u64 t; cvta.to.shared.u64 t, %1; cvt.u32.u64 %0, t; }" : "=r"(a) : "l"(p));
    return a;
}
__device__ __forceinline__ void cp_async16(uint32_t dst, const void* src) {
    asm volatile("cp.async.cg.shared.global [%0], [%1], 16;" :: "r"(dst), "l"(src) : "memory");
}
__device__ __forceinline__ void cp_commit() {
    asm volatile("cp.async.commit_group;" ::: "memory");
}
__device__ __forceinline__ void cp_wait1() {
    asm volatile("cp.async.wait_group 1;" ::: "memory");
}
__device__ __forceinline__ void cp_wait0() {
    asm volatile("cp.async.wait_group 0;" ::: "memory");
}
__device__ __forceinline__ void ldm_x4(uint32_t& r0, uint32_t& r1, uint32_t& r2, uint32_t& r3,
                                       uint32_t addr) {
    asm volatile("ldmatrix.sync.aligned.m8n8.x4.shared.b16 {%0,%1,%2,%3}, [%4];"
                 : "=r"(r0), "=r"(r1), "=r"(r2), "=r"(r3) : "r"(addr));
}
__device__ __forceinline__ void ldm_x4_t(uint32_t& r0, uint32_t& r1, uint32_t& r2, uint32_t& r3,
                                         uint32_t addr) {
    asm volatile("ldmatrix.sync.aligned.m8n8.x4.trans.shared.b16 {%0,%1,%2,%3}, [%4];"
                 : "=r"(r0), "=r"(r1), "=r"(r2), "=r"(r3) : "r"(addr));
}
__device__ __forceinline__ void mma_bf16(float* c, const uint32_t* a, const uint32_t* b) {
    asm volatile("mma.sync.aligned.m16n8k16.row.col.f32.bf16.bf16.f32 "
                 "{%0,%1,%2,%3}, {%4,%5,%6,%7}, {%8,%9}, {%0,%1,%2,%3};"
                 : "+f"(c[0]), "+f"(c[1]), "+f"(c[2]), "+f"(c[3])
                 : "r"(a[0]), "r"(a[1]), "r"(a[2]), "r"(a[3]), "r"(b[0]), "r"(b[1]));
}
__device__ __forceinline__ void mma_f16(float* c, const uint32_t* a, uint32_t b0, uint32_t b1) {
    asm volatile("mma.sync.aligned.m16n8k16.row.col.f32.f16.f16.f32 "
                 "{%0,%1,%2,%3}, {%4,%5,%6,%7}, {%8,%9}, {%0,%1,%2,%3};"
                 : "+f"(c[0]), "+f"(c[1]), "+f"(c[2]), "+f"(c[3])
                 : "r"(a[0]), "r"(a[1]), "r"(a[2]), "r"(a[3]), "r"(b0), "r"(b1));
}
// pack two fp32 into bf16x2 / f16x2: low half = f0, high half = f1
__device__ __forceinline__ uint32_t pack_bf16x2(float f0, float f1) {
    uint32_t r;
    asm("cvt.rn.bf16x2.f32 %0, %1, %2;" : "=r"(r) : "f"(f1), "f"(f0));
    return r;
}
__device__ __forceinline__ uint32_t pack_f16x2(float f0, float f1) {
    uint32_t r;
    asm("cvt.rn.f16x2.f32 %0, %1, %2;" : "=r"(r) : "f"(f1), "f"(f0));
    return r;
}
__device__ __forceinline__ float bf16rt(float x) {
    return __bfloat162float(__float2bfloat16(x));
}

// ================= split kernels: fp32 -> (hi, lo) bf16 =================
__device__ __forceinline__ void split_one(const float* __restrict__ src,
                                          __nv_bfloat16* __restrict__ hi,
                                          __nv_bfloat16* __restrict__ lo, int i)
{
    float4 v = ((const float4*)src)[i];
    __nv_bfloat16 h0 = __float2bfloat16(v.x), h1 = __float2bfloat16(v.y);
    __nv_bfloat16 h2 = __float2bfloat16(v.z), h3 = __float2bfloat16(v.w);
    __nv_bfloat16 l0 = __float2bfloat16(v.x - __bfloat162float(h0));
    __nv_bfloat16 l1 = __float2bfloat16(v.y - __bfloat162float(h1));
    __nv_bfloat16 l2 = __float2bfloat16(v.z - __bfloat162float(h2));
    __nv_bfloat16 l3 = __float2bfloat16(v.w - __bfloat162float(h3));
    __nv_bfloat162* hp = (__nv_bfloat162*)hi;
    __nv_bfloat162* lp = (__nv_bfloat162*)lo;
    hp[i * 2 + 0] = __nv_bfloat162(h0, h1);
    hp[i * 2 + 1] = __nv_bfloat162(h2, h3);
    lp[i * 2 + 0] = __nv_bfloat162(l0, l1);
    lp[i * 2 + 1] = __nv_bfloat162(l2, l3);
}

__global__ __launch_bounds__(256) void split_kernel(
    const float* __restrict__ src, __nv_bfloat16* __restrict__ hi,
    __nv_bfloat16* __restrict__ lo, int n4)
{
    int i = blockIdx.x * blockDim.x + threadIdx.x;
    if (i >= n4) return;
    split_one(src, hi, lo, i);
}

struct SplitSet {
    const float* src[4];
    __nv_bfloat16* hi[4];
    __nv_bfloat16* lo[4];
};
__global__ __launch_bounds__(256) void split4_kernel(SplitSet s, int n4)
{
    int i = blockIdx.x * blockDim.x + threadIdx.x;
    if (i >= n4) return;
    int t = blockIdx.y;
    split_one(s.src[t], s.hi[t], s.lo[t], i);
}

// ================= mma.sync GEMM core (CTA tile 128x128, BK=64) ==================
// MODE 0: fp32 out. MODE 2: fp16 out, scaled by mul.
#define GBK        64
#define TILE_B     (128 * 128)
#define STAGE_B    (4 * TILE_B)
#define GEMM_SMEM  (2 * STAGE_B)

#define T_AHI 0
#define T_ALO (1 * TILE_B)
#define T_BHI (2 * TILE_B)
#define T_BLO (3 * TILE_B)

template<int MODE>
__device__ __forceinline__ void gemm_tile_body(
    const __nv_bfloat16* __restrict__ Ahi, const __nv_bfloat16* __restrict__ Alo,
    const __nv_bfloat16* __restrict__ Bhi, const __nv_bfloat16* __restrict__ Blo,
    float* __restrict__ C, __half* __restrict__ Ch, float mul, int M, int N, int K,
    int m0, int n0, char* smem)
{
    const uint32_t sb = smem_u32(smem);
    const int tid = threadIdx.x;
    const int wid = tid >> 5;
    const int l   = tid & 31;
    const int wm  = wid & 3;
    const int wn  = wid >> 2;

    int lrow[4], ldst[4];
    #pragma unroll
    for (int i = 0; i < 4; i++) {
        int idx = tid + i * 256;
        int row = idx >> 3, c16 = idx & 7;
        lrow[i] = row;
        ldst[i] = row * 128 + ((c16 ^ (row & 7)) << 4);
    }

    auto issue_stage = [&](int c, int buf) {
        uint32_t s0 = sb + buf * STAGE_B;
        #pragma unroll
        for (int i = 0; i < 4; i++) {
            int row = lrow[i];
            int koff = c * GBK + ((tid + i * 256) & 7) * 8;
            cp_async16(s0 + T_AHI + ldst[i], Ahi + (size_t)(m0 + row) * K + koff);
            cp_async16(s0 + T_ALO + ldst[i], Alo + (size_t)(m0 + row) * K + koff);
            cp_async16(s0 + T_BHI + ldst[i], Bhi + (size_t)(n0 + row) * K + koff);
            cp_async16(s0 + T_BLO + ldst[i], Blo + (size_t)(n0 + row) * K + koff);
        }
        cp_commit();
    };

    const int a_rowoff = (l & 15);
    const int a_c16off = (l >> 4);
    const int b_rowoff = (l & 7) | ((l & 16) >> 1);
    const int b_c16off = (l >> 3) & 1;

    float acc[2][8][4];
    #pragma unroll
    for (int mi = 0; mi < 2; mi++)
        #pragma unroll
        for (int nj = 0; nj < 8; nj++)
            #pragma unroll
            for (int t = 0; t < 4; t++) acc[mi][nj][t] = 0.f;

    const int nchunks = K / GBK;
    issue_stage(0, 0);
    issue_stage(1, 1);

    for (int c = 0; c < nchunks; c++) {
        const int buf = c & 1;
        if (c < nchunks - 2) cp_wait1(); else cp_wait0();
        __syncthreads();

        const uint32_t s0 = sb + buf * STAGE_B;
        #pragma unroll
        for (int kk = 0; kk < 4; kk++) {
            uint32_t ahi[2][4], alo[2][4];
            #pragma unroll
            for (int mi = 0; mi < 2; mi++) {
                int row = wm * 32 + mi * 16 + a_rowoff;
                int c16 = kk * 2 + a_c16off;
                uint32_t ad = s0 + row * 128 + ((c16 ^ (row & 7)) << 4);
                ldm_x4(ahi[mi][0], ahi[mi][1], ahi[mi][2], ahi[mi][3], ad + T_AHI);
                ldm_x4(alo[mi][0], alo[mi][1], alo[mi][2], alo[mi][3], ad + T_ALO);
            }
            uint32_t bhi[8][2], blo[8][2];
            #pragma unroll
            for (int p = 0; p < 4; p++) {
                int row = wn * 64 + p * 16 + b_rowoff;
                int c16 = kk * 2 + b_c16off;
                uint32_t ad = s0 + row * 128 + ((c16 ^ (row & 7)) << 4);
                ldm_x4(bhi[2*p][0], bhi[2*p][1], bhi[2*p+1][0], bhi[2*p+1][1], ad + T_BHI);
                ldm_x4(blo[2*p][0], blo[2*p][1], blo[2*p+1][0], blo[2*p+1][1], ad + T_BLO);
            }
            #pragma unroll
            for (int mi = 0; mi < 2; mi++)
                #pragma unroll
                for (int nj = 0; nj < 8; nj++) {
                    mma_bf16(acc[mi][nj], ahi[mi], bhi[nj]);
                    mma_bf16(acc[mi][nj], ahi[mi], blo[nj]);
                    mma_bf16(acc[mi][nj], alo[mi], bhi[nj]);
                }
        }
        __syncthreads();
        if (c + 2 < nchunks) issue_stage(c + 2, buf);
    }

    const int er = l >> 2;
    const int ec = (l & 3) * 2;
    #pragma unroll
    for (int mi = 0; mi < 2; mi++) {
        int grow = m0 + wm * 32 + mi * 16 + er;
        #pragma unroll
        for (int nj = 0; nj < 8; nj++) {
            int gcol = n0 + wn * 64 + nj * 8 + ec;
            if (MODE == 0) {
                *(float2*)&C[(size_t)grow * N + gcol] =
                    make_float2(acc[mi][nj][0], acc[mi][nj][1]);
                *(float2*)&C[(size_t)(grow + 8) * N + gcol] =
                    make_float2(acc[mi][nj][2], acc[mi][nj][3]);
            } else {
                *(uint32_t*)&Ch[(size_t)grow * N + gcol] =
                    pack_f16x2(acc[mi][nj][0] * mul, acc[mi][nj][1] * mul);
                *(uint32_t*)&Ch[(size_t)(grow + 8) * N + gcol] =
                    pack_f16x2(acc[mi][nj][2] * mul, acc[mi][nj][3] * mul);
            }
        }
    }
}

__global__ __launch_bounds__(256) void gemm_f32out_kernel(
    const __nv_bfloat16* __restrict__ Ahi, const __nv_bfloat16* __restrict__ Alo,
    const __nv_bfloat16* __restrict__ Bhi, const __nv_bfloat16* __restrict__ Blo,
    float* __restrict__ C, int M, int N, int K)
{
    extern __shared__ char smem[];
    gemm_tile_body<0>(Ahi, Alo, Bhi, Blo, C, nullptr, 1.0f,
                      M, N, K, blockIdx.y * 128, blockIdx.x * 128, smem);
}

struct QKVSet {
    const __nv_bfloat16* bhi[3];
    const __nv_bfloat16* blo[3];
    __half* ch[3];
    float mul[3];
};
__global__ __launch_bounds__(256) void gemm_qkv_kernel(
    const __nv_bfloat16* __restrict__ Ahi, const __nv_bfloat16* __restrict__ Alo,
    QKVSet s, int M, int N, int K)
{
    extern __shared__ char smem[];
    const int z = blockIdx.z;
    gemm_tile_body<2>(Ahi, Alo, s.bhi[z], s.blo[z], nullptr, s.ch[z],
                      s.mul[z], M, N, K, blockIdx.y * 128, blockIdx.x * 128, smem);
}

// ============================================================
// Tensor-core flash attention v3 (causal) — fp16 single precision.
// Block: 256 threads (8 warps); BQ=128, BKV=64, hd=128.
// Warp w owns q-rows [w*16, w*16+16). Double-buffered KV stages.
// smem: Q 32KB + 2 stages x (K 16KB + V 16KB) = 96 KB.
// ============================================================
#define FT_Q     0
#define FT_STAGE 32768           // stage s at FT_STAGE + s*32768
#define FS_K     0
#define FS_V     16384
#define FLASH_TC_SMEM 98304

__device__ __forceinline__ uint32_t fsw(int row, int c16) {
    return (uint32_t)(row * 256 + ((c16 ^ ((row & 7) << 1)) << 4));
}

__global__ __launch_bounds__(256) void flash_attn_tc_kernel(
    const __half* __restrict__ qh, const __half* __restrict__ kh,
    const __half* __restrict__ vh,
    __nv_bfloat16* __restrict__ ohi, __nv_bfloat16* __restrict__ olo)
{
    extern __shared__ char fsm[];
    const uint32_t sb = smem_u32(fsm);
    const int tid = threadIdx.x;
    const int wid = tid >> 5;
    const int l   = tid & 31;
    const int qt = gridDim.x - 1 - blockIdx.x;   // longest-first scheduling
    const int h  = blockIdx.y;
    const int b  = blockIdx.z;
    const int q0 = qt * 128;

    // ---- load Q tile (128x128 fp16) ----
    const size_t gq = ((size_t)b * SEQ + q0) * DMODEL + h * HDIM;
    #pragma unroll
    for (int i = 0; i < 8; i++) {
        int idx = tid + i * 256;
        int row = idx >> 4, c16 = idx & 15;
        cp_async16(sb + FT_Q + fsw(row, c16), qh + gq + (size_t)row * DMODEL + c16 * 8);
    }
    cp_commit();

    auto issue_kv = [&](int kt, int sidx) {
        uint32_t s0 = sb + FT_STAGE + sidx * 32768;
        const size_t gkv = ((size_t)b * SEQ + kt * 64) * DMODEL + h * HDIM;
        #pragma unroll
        for (int i = 0; i < 4; i++) {
            int idx = tid + i * 256;
            int row = idx >> 4, c16 = idx & 15;
            uint32_t off = fsw(row, c16);
            size_t src = gkv + (size_t)row * DMODEL + c16 * 8;
            cp_async16(s0 + FS_K + off, kh + src);
            cp_async16(s0 + FS_V + off, vh + src);
        }
        cp_commit();
    };

    const int r  = l >> 2;
    const int cq = l & 3;
    const int a_rowoff = (l & 15);
    const int a_c16off = (l >> 4);
    const int b_rowoff = (l & 7) | ((l & 16) >> 1);
    const int b_c16off = (l >> 3) & 1;
    const int wrow0 = q0 + wid * 16;     // first global q-row owned by this warp

    float m0v = -1e30f, m1v = -1e30f, l0v = 0.f, l1v = 0.f;
    float O[16][4];
    #pragma unroll
    for (int g = 0; g < 16; g++)
        #pragma unroll
        for (int t = 0; t < 4; t++) O[g][t] = 0.f;

    const int nkt = 2 * qt + 2;          // kv tiles 0 .. 2qt+1
    issue_kv(0, 0);

    for (int kt = 0; kt < nkt; kt++) {
        const int sidx = kt & 1;
        if (kt + 1 < nkt) issue_kv(kt + 1, sidx ^ 1);
        if (kt + 1 < nkt) cp_wait1(); else cp_wait0();
        __syncthreads();

        const int col0 = kt * 64;
        if (col0 <= wrow0 + 15) {        // warp-level causal skip
            const uint32_t s0 = sb + FT_STAGE + sidx * 32768;

            // ---- scores S = Q @ K^T (fp16) ----
            float s[8][4];
            #pragma unroll
            for (int nj = 0; nj < 8; nj++)
                #pragma unroll
                for (int t = 0; t < 4; t++) s[nj][t] = 0.f;

            #pragma unroll
            for (int j = 0; j < 8; j++) {
                int arow = wid * 16 + a_rowoff;
                uint32_t ah[4];
                ldm_x4(ah[0], ah[1], ah[2], ah[3], sb + FT_Q + fsw(arow, 2 * j + a_c16off));

                uint32_t bh[8][2];
                #pragma unroll
                for (int p = 0; p < 4; p++) {
                    int brow = p * 16 + b_rowoff;
                    uint32_t bad = s0 + FS_K + fsw(brow, 2 * j + b_c16off);
                    ldm_x4(bh[2*p][0], bh[2*p][1], bh[2*p+1][0], bh[2*p+1][1], bad);
                }
                #pragma unroll
                for (int nj = 0; nj < 8; nj++)
                    mma_f16(s[nj], ah, bh[nj][0], bh[nj][1]);
            }

            // ---- causal mask (partial tiles only) ----
            if (col0 + 63 > wrow0) {
                #pragma unroll
                for (int nj = 0; nj < 8; nj++)
                    #pragma unroll
                    for (int t = 0; t < 4; t++) {
                        int coll = col0 + nj * 8 + 2 * cq + (t & 1);
                        int rowl = wrow0 + r + ((t >> 1) << 3);
                        if (coll > rowl) s[nj][t] = -1e30f;
                    }
            }

            // ---- online softmax (warp-private rows) ----
            float mx0 = -1e30f, mx1 = -1e30f;
            #pragma unroll
            for (int nj = 0; nj < 8; nj++) {
                mx0 = fmaxf(mx0, fmaxf(s[nj][0], s[nj][1]));
                mx1 = fmaxf(mx1, fmaxf(s[nj][2], s[nj][3]));
            }
            mx0 = fmaxf(mx0, __shfl_xor_sync(0xffffffffu, mx0, 1));
            mx0 = fmaxf(mx0, __shfl_xor_sync(0xffffffffu, mx0, 2));
            mx1 = fmaxf(mx1, __shfl_xor_sync(0xffffffffu, mx1, 1));
            mx1 = fmaxf(mx1, __shfl_xor_sync(0xffffffffu, mx1, 2));

            float mn0 = fmaxf(m0v, mx0), mn1 = fmaxf(m1v, mx1);
            float al0 = __expf(m0v - mn0), al1 = __expf(m1v - mn1);
            m0v = mn0; m1v = mn1;

            #pragma unroll
            for (int g = 0; g < 16; g++) {
                O[g][0] *= al0; O[g][1] *= al0;
                O[g][2] *= al1; O[g][3] *= al1;
            }

            float rs0 = 0.f, rs1 = 0.f;
            #pragma unroll
            for (int nj = 0; nj < 8; nj++) {
                s[nj][0] = __expf(s[nj][0] - mn0);
                s[nj][1] = __expf(s[nj][1] - mn0);
                s[nj][2] = __expf(s[nj][2] - mn1);
                s[nj][3] = __expf(s[nj][3] - mn1);
                rs0 += s[nj][0] + s[nj][1];
                rs1 += s[nj][2] + s[nj][3];
            }
            rs0 += __shfl_xor_sync(0xffffffffu, rs0, 1);
            rs0 += __shfl_xor_sync(0xffffffffu, rs0, 2);
            rs1 += __shfl_xor_sync(0xffffffffu, rs1, 1);
            rs1 += __shfl_xor_sync(0xffffffffu, rs1, 2);
            l0v = l0v * al0 + rs0;
            l1v = l1v * al1 + rs1;

            // ---- O += P @ V (fp16) ----
            #pragma unroll
            for (int j = 0; j < 4; j++) {
                uint32_t pa[4];
                pa[0] = pack_f16x2(s[2*j][0],   s[2*j][1]);
                pa[1] = pack_f16x2(s[2*j][2],   s[2*j][3]);
                pa[2] = pack_f16x2(s[2*j+1][0], s[2*j+1][1]);
                pa[3] = pack_f16x2(s[2*j+1][2], s[2*j+1][3]);
                #pragma unroll
                for (int g = 0; g < 8; g++) {
                    int vrow = j * 16 + (l & 15);
                    uint32_t vad = s0 + FS_V + fsw(vrow, 2 * g + (l >> 4));
                    uint32_t v0, v1, v2, v3;
                    ldm_x4_t(v0, v1, v2, v3, vad);
                    mma_f16(O[2*g],     pa, v0, v1);
                    mma_f16(O[2*g + 1], pa, v2, v3);
                }
            }
        }
        __syncthreads();   // release stage buffer for the next prefetch
    }

    // ---- epilogue: divide by l, write hi/lo bf16 ----
    const float i0 = 1.0f / l0v;
    const float i1 = 1.0f / l1v;
    const size_t obase = ((size_t)b * SEQ + q0 + wid * 16 + r) * DMODEL + h * HDIM;
    #pragma unroll
    for (int g = 0; g < 16; g++) {
        int col = g * 8 + 2 * cq;
        float a0 = O[g][0] * i0, a1 = O[g][1] * i0;
        float a2 = O[g][2] * i1, a3 = O[g][3] * i1;
        *(uint32_t*)&ohi[obase + col] = pack_bf16x2(a0, a1);
        *(uint32_t*)&olo[obase + col] = pack_bf16x2(a0 - bf16rt(a0), a1 - bf16rt(a1));
        *(uint32_t*)&ohi[obase + (size_t)8 * DMODEL + col] = pack_bf16x2(a2, a3);
        *(uint32_t*)&olo[obase + (size_t)8 * DMODEL + col] =
            pack_bf16x2(a2 - bf16rt(a2), a3 - bf16rt(a3));
    }
}

// ============================================================
// launcher
// ============================================================
extern "C" void kernel_launch(void* const* d_in, const int* in_sizes, int n_in,
                              void* d_out, int out_size)
{
    const float* x  = (const float*)d_in[0];
    const float* Wq = (const float*)d_in[1];
    const float* Wk = (const float*)d_in[2];
    const float* Wv = (const float*)d_in[3];
    const float* Wp = (const float*)d_in[4];
    float* out = (float*)d_out;

    void *qh, *kh, *vh, *aohi, *aolo;
    cudaGetSymbolAddress(&qh, g_qh);
    cudaGetSymbolAddress(&kh, g_kh);
    cudaGetSymbolAddress(&vh, g_vh);
    cudaGetSymbolAddress(&aohi, g_aohi);
    cudaGetSymbolAddress(&aolo, g_aolo);

    void *xhi, *xlo;
    void *wqhi, *wqlo, *wkhi, *wklo, *wvhi, *wvlo, *wphi, *wplo;
    cudaGetSymbolAddress(&xhi,  g_xhi);  cudaGetSymbolAddress(&xlo,  g_xlo);
    cudaGetSymbolAddress(&wqhi, g_wqhi); cudaGetSymbolAddress(&wqlo, g_wqlo);
    cudaGetSymbolAddress(&wkhi, g_wkhi); cudaGetSymbolAddress(&wklo, g_wklo);
    cudaGetSymbolAddress(&wvhi, g_wvhi); cudaGetSymbolAddress(&wvlo, g_wvlo);
    cudaGetSymbolAddress(&wphi, g_wphi); cudaGetSymbolAddress(&wplo, g_wplo);

    cudaFuncSetAttribute(flash_attn_tc_kernel,
                         cudaFuncAttributeMaxDynamicSharedMemorySize, FLASH_TC_SMEM);
    cudaFuncSetAttribute(gemm_f32out_kernel,
                         cudaFuncAttributeMaxDynamicSharedMemorySize, GEMM_SMEM);
    cudaFuncSetAttribute(gemm_qkv_kernel,
                         cudaFuncAttributeMaxDynamicSharedMemorySize, GEMM_SMEM);

    const int nx4 = (MROWS * DMODEL) / 4;
    const int nw4 = (DMODEL * DMODEL) / 4;

    split_kernel<<<(nx4 + 255) / 256, 256>>>(x, (__nv_bfloat16*)xhi, (__nv_bfloat16*)xlo, nx4);
    {
        SplitSet ss;
        ss.src[0] = Wq; ss.hi[0] = (__nv_bfloat16*)wqhi; ss.lo[0] = (__nv_bfloat16*)wqlo;
        ss.src[1] = Wk; ss.hi[1] = (__nv_bfloat16*)wkhi; ss.lo[1] = (__nv_bfloat16*)wklo;
        ss.src[2] = Wv; ss.hi[2] = (__nv_bfloat16*)wvhi; ss.lo[2] = (__nv_bfloat16*)wvlo;
        ss.src[3] = Wp; ss.hi[3] = (__nv_bfloat16*)wphi; ss.lo[3] = (__nv_bfloat16*)wplo;
        dim3 sg((nw4 + 255) / 256, 4);
        split4_kernel<<<sg, 256>>>(ss, nw4);
    }

    const float scale = 0.08838834764831845f;  // 1/sqrt(128), folded into Q

    {
        QKVSet qs;
        qs.bhi[0] = (const __nv_bfloat16*)wqhi; qs.blo[0] = (const __nv_bfloat16*)wqlo;
        qs.ch[0] = (__half*)qh; qs.mul[0] = scale;
        qs.bhi[1] = (const __nv_bfloat16*)wkhi; qs.blo[1] = (const __nv_bfloat16*)wklo;
        qs.ch[1] = (__half*)kh; qs.mul[1] = 1.0f;
        qs.bhi[2] = (const __nv_bfloat16*)wvhi; qs.blo[2] = (const __nv_bfloat16*)wvlo;
        qs.ch[2] = (__half*)vh; qs.mul[2] = 1.0f;
        dim3 qg(DMODEL / 128, MROWS / 128, 3);   // (16, 32, 3)
        gemm_qkv_kernel<<<qg, 256, GEMM_SMEM>>>(
            (const __nv_bfloat16*)xhi, (const __nv_bfloat16*)xlo,
            qs, MROWS, DMODEL, DMODEL);
    }

    dim3 fgrid(SEQ / 128, NHEAD, BATCH);     // (16, 16, 2)
    flash_attn_tc_kernel<<<fgrid, 256, FLASH_TC_SMEM>>>(
        (const __half*)qh, (const __half*)kh, (const __half*)vh,
        (__nv_bfloat16*)aohi, (__nv_bfloat16*)aolo);

    dim3 ggrid(DMODEL / 128, MROWS / 128);   // (16, 32)
    gemm_f32out_kernel<<<ggrid, 256, GEMM_SMEM>>>(
        (const __nv_bfloat16*)aohi, (const __nv_bfloat16*)aolo,
        (const __nv_bfloat16*)wphi, (const __nv_bfloat16*)wplo,
        out, MROWS, DMODEL, DMODEL);
}

// round 11
// speedup vs baseline: 1.6207x; 1.3924x over previous
#include <cuda_runtime.h>
#include <cuda_bf16.h>
#include <cuda_fp16.h>
#include <stdint.h>
#include <math.h>

// Problem constants (fixed): B=2, S=2048, D=2048, H=16
#define BATCH  2
#define SEQ    2048
#define DMODEL 2048
#define NHEAD  16
#define HDIM   128
#define MROWS  (BATCH * SEQ)   // 4096

// ================= scratch (device globals: allocation-free) =================
__device__ __half g_xh [(size_t)MROWS * DMODEL];
__device__ __half g_qh [(size_t)MROWS * DMODEL];
__device__ __half g_kh [(size_t)MROWS * DMODEL];
__device__ __half g_vh [(size_t)MROWS * DMODEL];
__device__ __half g_aoh[(size_t)MROWS * DMODEL];

__device__ __half g_wqh[(size_t)DMODEL * DMODEL];
__device__ __half g_wql[(size_t)DMODEL * DMODEL];
__device__ __half g_wkh[(size_t)DMODEL * DMODEL];
__device__ __half g_wkl[(size_t)DMODEL * DMODEL];
__device__ __half g_wvh[(size_t)DMODEL * DMODEL];
__device__ __half g_wvl[(size_t)DMODEL * DMODEL];
__device__ __half g_wph[(size_t)DMODEL * DMODEL];
__device__ __half g_wpl[(size_t)DMODEL * DMODEL];

// ================= PTX helpers (baseline features only) ======
__device__ __forceinline__ uint32_t smem_u32(const void* p) {
    uint32_t a;
    asm("{ .reg .u64 t; cvta.to.shared.u64 t, %1; cvt.u32.u64 %0, t; }" : "=r"(a) : "l"(p));
    return a;
}
__device__ __forceinline__ void cp_async16(uint32_t dst, const void* src) {
    asm volatile("cp.async.cg.shared.global [%0], [%1], 16;" :: "r"(dst), "l"(src) : "memory");
}
__device__ __forceinline__ void cp_commit() {
    asm volatile("cp.async.commit_group;" ::: "memory");
}
__device__ __forceinline__ void cp_wait1() {
    asm volatile("cp.async.wait_group 1;" ::: "memory");
}
__device__ __forceinline__ void cp_wait0() {
    asm volatile("cp.async.wait_group 0;" ::: "memory");
}
__device__ __forceinline__ void ldm_x4(uint32_t& r0, uint32_t& r1, uint32_t& r2, uint32_t& r3,
                                       uint32_t addr) {
    asm volatile("ldmatrix.sync.aligned.m8n8.x4.shared.b16 {%0,%1,%2,%3}, [%4];"
                 : "=r"(r0), "=r"(r1), "=r"(r2), "=r"(r3) : "r"(addr));
}
__device__ __forceinline__ void ldm_x4_t(uint32_t& r0, uint32_t& r1, uint32_t& r2, uint32_t& r3,
                                         uint32_t addr) {
    asm volatile("ldmatrix.sync.aligned.m8n8.x4.trans.shared.b16 {%0,%1,%2,%3}, [%4];"
                 : "=r"(r0), "=r"(r1), "=r"(r2), "=r"(r3) : "r"(addr));
}
__device__ __forceinline__ void mma_f16(float* c, const uint32_t* a, uint32_t b0, uint32_t b1) {
    asm volatile("mma.sync.aligned.m16n8k16.row.col.f32.f16.f16.f32 "
                 "{%0,%1,%2,%3}, {%4,%5,%6,%7}, {%8,%9}, {%0,%1,%2,%3};"
                 : "+f"(c[0]), "+f"(c[1]), "+f"(c[2]), "+f"(c[3])
                 : "r"(a[0]), "r"(a[1]), "r"(a[2]), "r"(a[3]), "r"(b0), "r"(b1));
}
__device__ __forceinline__ uint32_t pack_f16x2(float f0, float f1) {
    uint32_t r;
    asm("cvt.rn.f16x2.f32 %0, %1, %2;" : "=r"(r) : "f"(f1), "f"(f0));
    return r;
}

// ================= conversion kernels =================
// fp32 -> fp16 single
__global__ __launch_bounds__(256) void cvt_f16_kernel(
    const float* __restrict__ src, __half* __restrict__ dst, int n4)
{
    int i = blockIdx.x * blockDim.x + threadIdx.x;
    if (i >= n4) return;
    float4 v = ((const float4*)src)[i];
    uint2 o;
    o.x = pack_f16x2(v.x, v.y);
    o.y = pack_f16x2(v.z, v.w);
    ((uint2*)dst)[i] = o;
}

// fused 4-weight split: fp32 -> (hi, lo) fp16; blockIdx.y selects tensor
struct SplitSetH {
    const float* src[4];
    __half* hi[4];
    __half* lo[4];
};
__global__ __launch_bounds__(256) void split4h_kernel(SplitSetH s, int n4)
{
    int i = blockIdx.x * blockDim.x + threadIdx.x;
    if (i >= n4) return;
    int t = blockIdx.y;
    float4 v = ((const float4*)s.src[t])[i];
    __half h0 = __float2half(v.x), h1 = __float2half(v.y);
    __half h2 = __float2half(v.z), h3 = __float2half(v.w);
    float l0 = v.x - __half2float(h0), l1 = v.y - __half2float(h1);
    float l2 = v.z - __half2float(h2), l3 = v.w - __half2float(h3);
    uint2 ho, lo;
    ho.x = pack_f16x2(__half2float(h0), __half2float(h1));
    ho.y = pack_f16x2(__half2float(h2), __half2float(h3));
    lo.x = pack_f16x2(l0, l1);
    lo.y = pack_f16x2(l2, l3);
    ((uint2*)s.hi[t])[i] = ho;
    ((uint2*)s.lo[t])[i] = lo;
}

// ================= fp16 2-term GEMM: C[M,N] = A[M,K] @ (Bh+Bl)[N,K]^T =========
// A single fp16; B split hi/lo fp16. CTA tile 128x128, BK=64, 256 threads.
#define GBK        64
#define TILE_B     (128 * 128)               // 16 KB per tile (128 rows x 128 B)
#define STAGE_B    (3 * TILE_B)              // A, Bh, Bl
#define GEMM_SMEM  (2 * STAGE_B)             // 98304 B

#define T_A  0
#define T_BH (1 * TILE_B)
#define T_BL (2 * TILE_B)

// MODE 0: fp32 out. MODE 2: fp16 out scaled by mul.
template<int MODE>
__device__ __forceinline__ void gemm_tile_body(
    const __half* __restrict__ A, const __half* __restrict__ Bh,
    const __half* __restrict__ Bl,
    float* __restrict__ C, __half* __restrict__ Ch, float mul, int M, int N, int K,
    int m0, int n0, char* smem)
{
    const uint32_t sb = smem_u32(smem);
    const int tid = threadIdx.x;
    const int wid = tid >> 5;
    const int l   = tid & 31;
    const int wm  = wid & 3;
    const int wn  = wid >> 2;

    int lrow[4], ldst[4];
    #pragma unroll
    for (int i = 0; i < 4; i++) {
        int idx = tid + i * 256;
        int row = idx >> 3, c16 = idx & 7;
        lrow[i] = row;
        ldst[i] = row * 128 + ((c16 ^ (row & 7)) << 4);
    }

    auto issue_stage = [&](int c, int buf) {
        uint32_t s0 = sb + buf * STAGE_B;
        #pragma unroll
        for (int i = 0; i < 4; i++) {
            int row = lrow[i];
            int koff = c * GBK + ((tid + i * 256) & 7) * 8;
            cp_async16(s0 + T_A  + ldst[i], A  + (size_t)(m0 + row) * K + koff);
            cp_async16(s0 + T_BH + ldst[i], Bh + (size_t)(n0 + row) * K + koff);
            cp_async16(s0 + T_BL + ldst[i], Bl + (size_t)(n0 + row) * K + koff);
        }
        cp_commit();
    };

    const int a_rowoff = (l & 15);
    const int a_c16off = (l >> 4);
    const int b_rowoff = (l & 7) | ((l & 16) >> 1);
    const int b_c16off = (l >> 3) & 1;

    float acc[2][8][4];
    #pragma unroll
    for (int mi = 0; mi < 2; mi++)
        #pragma unroll
        for (int nj = 0; nj < 8; nj++)
            #pragma unroll
            for (int t = 0; t < 4; t++) acc[mi][nj][t] = 0.f;

    const int nchunks = K / GBK;
    issue_stage(0, 0);
    issue_stage(1, 1);

    for (int c = 0; c < nchunks; c++) {
        const int buf = c & 1;
        if (c < nchunks - 2) cp_wait1(); else cp_wait0();
        __syncthreads();

        const uint32_t s0 = sb + buf * STAGE_B;
        #pragma unroll
        for (int kk = 0; kk < 4; kk++) {
            uint32_t a[2][4];
            #pragma unroll
            for (int mi = 0; mi < 2; mi++) {
                int row = wm * 32 + mi * 16 + a_rowoff;
                int c16 = kk * 2 + a_c16off;
                uint32_t ad = s0 + T_A + row * 128 + ((c16 ^ (row & 7)) << 4);
                ldm_x4(a[mi][0], a[mi][1], a[mi][2], a[mi][3], ad);
            }
            uint32_t bh[8][2], bl[8][2];
            #pragma unroll
            for (int p = 0; p < 4; p++) {
                int row = wn * 64 + p * 16 + b_rowoff;
                int c16 = kk * 2 + b_c16off;
                uint32_t ad = s0 + row * 128 + ((c16 ^ (row & 7)) << 4);
                ldm_x4(bh[2*p][0], bh[2*p][1], bh[2*p+1][0], bh[2*p+1][1], ad + T_BH);
                ldm_x4(bl[2*p][0], bl[2*p][1], bl[2*p+1][0], bl[2*p+1][1], ad + T_BL);
            }
            #pragma unroll
            for (int mi = 0; mi < 2; mi++)
                #pragma unroll
                for (int nj = 0; nj < 8; nj++) {
                    mma_f16(acc[mi][nj], a[mi], bh[nj][0], bh[nj][1]);
                    mma_f16(acc[mi][nj], a[mi], bl[nj][0], bl[nj][1]);
                }
        }
        __syncthreads();
        if (c + 2 < nchunks) issue_stage(c + 2, buf);
    }

    const int er = l >> 2;
    const int ec = (l & 3) * 2;
    #pragma unroll
    for (int mi = 0; mi < 2; mi++) {
        int grow = m0 + wm * 32 + mi * 16 + er;
        #pragma unroll
        for (int nj = 0; nj < 8; nj++) {
            int gcol = n0 + wn * 64 + nj * 8 + ec;
            if (MODE == 0) {
                *(float2*)&C[(size_t)grow * N + gcol] =
                    make_float2(acc[mi][nj][0], acc[mi][nj][1]);
                *(float2*)&C[(size_t)(grow + 8) * N + gcol] =
                    make_float2(acc[mi][nj][2], acc[mi][nj][3]);
            } else {
                *(uint32_t*)&Ch[(size_t)grow * N + gcol] =
                    pack_f16x2(acc[mi][nj][0] * mul, acc[mi][nj][1] * mul);
                *(uint32_t*)&Ch[(size_t)(grow + 8) * N + gcol] =
                    pack_f16x2(acc[mi][nj][2] * mul, acc[mi][nj][3] * mul);
            }
        }
    }
}

__global__ __launch_bounds__(256) void gemm_f32out_kernel(
    const __half* __restrict__ A, const __half* __restrict__ Bh,
    const __half* __restrict__ Bl, float* __restrict__ C, int M, int N, int K)
{
    extern __shared__ char smem[];
    gemm_tile_body<0>(A, Bh, Bl, C, nullptr, 1.0f,
                      M, N, K, blockIdx.y * 128, blockIdx.x * 128, smem);
}

struct QKVSet {
    const __half* bh[3];
    const __half* bl[3];
    __half* ch[3];
    float mul[3];
};
__global__ __launch_bounds__(256) void gemm_qkv_kernel(
    const __half* __restrict__ A, QKVSet s, int M, int N, int K)
{
    extern __shared__ char smem[];
    const int z = blockIdx.z;
    gemm_tile_body<2>(A, s.bh[z], s.bl[z], nullptr, s.ch[z],
                      s.mul[z], M, N, K, blockIdx.y * 128, blockIdx.x * 128, smem);
}

// ============================================================
// Tensor-core flash attention v3 (causal) — fp16 single precision.
// Block: 256 threads (8 warps); BQ=128, BKV=64, hd=128.
// Double-buffered KV stages; warp-level causal skip; fp16 output.
// smem: Q 32KB + 2 stages x (K 16KB + V 16KB) = 96 KB.
// ============================================================
#define FT_Q     0
#define FT_STAGE 32768
#define FS_K     0
#define FS_V     16384
#define FLASH_TC_SMEM 98304

__device__ __forceinline__ uint32_t fsw(int row, int c16) {
    return (uint32_t)(row * 256 + ((c16 ^ ((row & 7) << 1)) << 4));
}

__global__ __launch_bounds__(256) void flash_attn_tc_kernel(
    const __half* __restrict__ qh, const __half* __restrict__ kh,
    const __half* __restrict__ vh, __half* __restrict__ oh)
{
    extern __shared__ char fsm[];
    const uint32_t sb = smem_u32(fsm);
    const int tid = threadIdx.x;
    const int wid = tid >> 5;
    const int l   = tid & 31;
    const int qt = gridDim.x - 1 - blockIdx.x;   // longest-first scheduling
    const int h  = blockIdx.y;
    const int b  = blockIdx.z;
    const int q0 = qt * 128;

    const size_t gq = ((size_t)b * SEQ + q0) * DMODEL + h * HDIM;
    #pragma unroll
    for (int i = 0; i < 8; i++) {
        int idx = tid + i * 256;
        int row = idx >> 4, c16 = idx & 15;
        cp_async16(sb + FT_Q + fsw(row, c16), qh + gq + (size_t)row * DMODEL + c16 * 8);
    }
    cp_commit();

    auto issue_kv = [&](int kt, int sidx) {
        uint32_t s0 = sb + FT_STAGE + sidx * 32768;
        const size_t gkv = ((size_t)b * SEQ + kt * 64) * DMODEL + h * HDIM;
        #pragma unroll
        for (int i = 0; i < 4; i++) {
            int idx = tid + i * 256;
            int row = idx >> 4, c16 = idx & 15;
            uint32_t off = fsw(row, c16);
            size_t src = gkv + (size_t)row * DMODEL + c16 * 8;
            cp_async16(s0 + FS_K + off, kh + src);
            cp_async16(s0 + FS_V + off, vh + src);
        }
        cp_commit();
    };

    const int r  = l >> 2;
    const int cq = l & 3;
    const int a_rowoff = (l & 15);
    const int a_c16off = (l >> 4);
    const int b_rowoff = (l & 7) | ((l & 16) >> 1);
    const int b_c16off = (l >> 3) & 1;
    const int wrow0 = q0 + wid * 16;

    float m0v = -1e30f, m1v = -1e30f, l0v = 0.f, l1v = 0.f;
    float O[16][4];
    #pragma unroll
    for (int g = 0; g < 16; g++)
        #pragma unroll
        for (int t = 0; t < 4; t++) O[g][t] = 0.f;

    const int nkt = 2 * qt + 2;
    issue_kv(0, 0);

    for (int kt = 0; kt < nkt; kt++) {
        const int sidx = kt & 1;
        if (kt + 1 < nkt) issue_kv(kt + 1, sidx ^ 1);
        if (kt + 1 < nkt) cp_wait1(); else cp_wait0();
        __syncthreads();

        const int col0 = kt * 64;
        if (col0 <= wrow0 + 15) {        // warp-level causal skip
            const uint32_t s0 = sb + FT_STAGE + sidx * 32768;

            float s[8][4];
            #pragma unroll
            for (int nj = 0; nj < 8; nj++)
                #pragma unroll
                for (int t = 0; t < 4; t++) s[nj][t] = 0.f;

            #pragma unroll
            for (int j = 0; j < 8; j++) {
                int arow = wid * 16 + a_rowoff;
                uint32_t ah[4];
                ldm_x4(ah[0], ah[1], ah[2], ah[3], sb + FT_Q + fsw(arow, 2 * j + a_c16off));

                uint32_t bh[8][2];
                #pragma unroll
                for (int p = 0; p < 4; p++) {
                    int brow = p * 16 + b_rowoff;
                    uint32_t bad = s0 + FS_K + fsw(brow, 2 * j + b_c16off);
                    ldm_x4(bh[2*p][0], bh[2*p][1], bh[2*p+1][0], bh[2*p+1][1], bad);
                }
                #pragma unroll
                for (int nj = 0; nj < 8; nj++)
                    mma_f16(s[nj], ah, bh[nj][0], bh[nj][1]);
            }

            if (col0 + 63 > wrow0) {
                #pragma unroll
                for (int nj = 0; nj < 8; nj++)
                    #pragma unroll
                    for (int t = 0; t < 4; t++) {
                        int coll = col0 + nj * 8 + 2 * cq + (t & 1);
                        int rowl = wrow0 + r + ((t >> 1) << 3);
                        if (coll > rowl) s[nj][t] = -1e30f;
                    }
            }

            float mx0 = -1e30f, mx1 = -1e30f;
            #pragma unroll
            for (int nj = 0; nj < 8; nj++) {
                mx0 = fmaxf(mx0, fmaxf(s[nj][0], s[nj][1]));
                mx1 = fmaxf(mx1, fmaxf(s[nj][2], s[nj][3]));
            }
            mx0 = fmaxf(mx0, __shfl_xor_sync(0xffffffffu, mx0, 1));
            mx0 = fmaxf(mx0, __shfl_xor_sync(0xffffffffu, mx0, 2));
            mx1 = fmaxf(mx1, __shfl_xor_sync(0xffffffffu, mx1, 1));
            mx1 = fmaxf(mx1, __shfl_xor_sync(0xffffffffu, mx1, 2));

            float mn0 = fmaxf(m0v, mx0), mn1 = fmaxf(m1v, mx1);
            float al0 = __expf(m0v - mn0), al1 = __expf(m1v - mn1);
            m0v = mn0; m1v = mn1;

            #pragma unroll
            for (int g = 0; g < 16; g++) {
                O[g][0] *= al0; O[g][1] *= al0;
                O[g][2] *= al1; O[g][3] *= al1;
            }

            float rs0 = 0.f, rs1 = 0.f;
            #pragma unroll
            for (int nj = 0; nj < 8; nj++) {
                s[nj][0] = __expf(s[nj][0] - mn0);
                s[nj][1] = __expf(s[nj][1] - mn0);
                s[nj][2] = __expf(s[nj][2] - mn1);
                s[nj][3] = __expf(s[nj][3] - mn1);
                rs0 += s[nj][0] + s[nj][1];
                rs1 += s[nj][2] + s[nj][3];
            }
            rs0 += __shfl_xor_sync(0xffffffffu, rs0, 1);
            rs0 += __shfl_xor_sync(0xffffffffu, rs0, 2);
            rs1 += __shfl_xor_sync(0xffffffffu, rs1, 1);
            rs1 += __shfl_xor_sync(0xffffffffu, rs1, 2);
            l0v = l0v * al0 + rs0;
            l1v = l1v * al1 + rs1;

            #pragma unroll
            for (int j = 0; j < 4; j++) {
                uint32_t pa[4];
                pa[0] = pack_f16x2(s[2*j][0],   s[2*j][1]);
                pa[1] = pack_f16x2(s[2*j][2],   s[2*j][3]);
                pa[2] = pack_f16x2(s[2*j+1][0], s[2*j+1][1]);
                pa[3] = pack_f16x2(s[2*j+1][2], s[2*j+1][3]);
                #pragma unroll
                for (int g = 0; g < 8; g++) {
                    int vrow = j * 16 + (l & 15);
                    uint32_t vad = s0 + FS_V + fsw(vrow, 2 * g + (l >> 4));
                    uint32_t v0, v1, v2, v3;
                    ldm_x4_t(v0, v1, v2, v3, vad);
                    mma_f16(O[2*g],     pa, v0, v1);
                    mma_f16(O[2*g + 1], pa, v2, v3);
                }
            }
        }
        __syncthreads();
    }

    // ---- epilogue: divide by l, write fp16 ----
    const float i0 = 1.0f / l0v;
    const float i1 = 1.0f / l1v;
    const size_t obase = ((size_t)b * SEQ + q0 + wid * 16 + r) * DMODEL + h * HDIM;
    #pragma unroll
    for (int g = 0; g < 16; g++) {
        int col = g * 8 + 2 * cq;
        *(uint32_t*)&oh[obase + col] = pack_f16x2(O[g][0] * i0, O[g][1] * i0);
        *(uint32_t*)&oh[obase + (size_t)8 * DMODEL + col] =
            pack_f16x2(O[g][2] * i1, O[g][3] * i1);
    }
}

// ============================================================
// launcher
// ============================================================
extern "C" void kernel_launch(void* const* d_in, const int* in_sizes, int n_in,
                              void* d_out, int out_size)
{
    const float* x  = (const float*)d_in[0];
    const float* Wq = (const float*)d_in[1];
    const float* Wk = (const float*)d_in[2];
    const float* Wv = (const float*)d_in[3];
    const float* Wp = (const float*)d_in[4];
    float* out = (float*)d_out;

    void *xh, *qh, *kh, *vh, *aoh;
    cudaGetSymbolAddress(&xh,  g_xh);
    cudaGetSymbolAddress(&qh,  g_qh);
    cudaGetSymbolAddress(&kh,  g_kh);
    cudaGetSymbolAddress(&vh,  g_vh);
    cudaGetSymbolAddress(&aoh, g_aoh);

    void *wqh, *wql, *wkh, *wkl, *wvh, *wvl, *wph, *wpl;
    cudaGetSymbolAddress(&wqh, g_wqh); cudaGetSymbolAddress(&wql, g_wql);
    cudaGetSymbolAddress(&wkh, g_wkh); cudaGetSymbolAddress(&wkl, g_wkl);
    cudaGetSymbolAddress(&wvh, g_wvh); cudaGetSymbolAddress(&wvl, g_wvl);
    cudaGetSymbolAddress(&wph, g_wph); cudaGetSymbolAddress(&wpl, g_wpl);

    cudaFuncSetAttribute(flash_attn_tc_kernel,
                         cudaFuncAttributeMaxDynamicSharedMemorySize, FLASH_TC_SMEM);
    cudaFuncSetAttribute(gemm_f32out_kernel,
                         cudaFuncAttributeMaxDynamicSharedMemorySize, GEMM_SMEM);
    cudaFuncSetAttribute(gemm_qkv_kernel,
                         cudaFuncAttributeMaxDynamicSharedMemorySize, GEMM_SMEM);

    const int nx4 = (MROWS * DMODEL) / 4;
    const int nw4 = (DMODEL * DMODEL) / 4;

    cvt_f16_kernel<<<(nx4 + 255) / 256, 256>>>(x, (__half*)xh, nx4);
    {
        SplitSetH ss;
        ss.src[0] = Wq; ss.hi[0] = (__half*)wqh; ss.lo[0] = (__half*)wql;
        ss.src[1] = Wk; ss.hi[1] = (__half*)wkh; ss.lo[1] = (__half*)wkl;
        ss.src[2] = Wv; ss.hi[2] = (__half*)wvh; ss.lo[2] = (__half*)wvl;
        ss.src[3] = Wp; ss.hi[3] = (__half*)wph; ss.lo[3] = (__half*)wpl;
        dim3 sg((nw4 + 255) / 256, 4);
        split4h_kernel<<<sg, 256>>>(ss, nw4);
    }

    const float scale = 0.08838834764831845f;  // 1/sqrt(128), folded into Q

    {
        QKVSet qs;
        qs.bh[0] = (const __half*)wqh; qs.bl[0] = (const __half*)wql;
        qs.ch[0] = (__half*)qh; qs.mul[0] = scale;
        qs.bh[1] = (const __half*)wkh; qs.bl[1] = (const __half*)wkl;
        qs.ch[1] = (__half*)kh; qs.mul[1] = 1.0f;
        qs.bh[2] = (const __half*)wvh; qs.bl[2] = (const __half*)wvl;
        qs.ch[2] = (__half*)vh; qs.mul[2] = 1.0f;
        dim3 qg(DMODEL / 128, MROWS / 128, 3);   // (16, 32, 3)
        gemm_qkv_kernel<<<qg, 256, GEMM_SMEM>>>(
            (const __half*)xh, qs, MROWS, DMODEL, DMODEL);
    }

    dim3 fgrid(SEQ / 128, NHEAD, BATCH);     // (16, 16, 2)
    flash_attn_tc_kernel<<<fgrid, 256, FLASH_TC_SMEM>>>(
        (const __half*)qh, (const __half*)kh, (const __half*)vh, (__half*)aoh);

    dim3 ggrid(DMODEL / 128, MROWS / 128);   // (16, 32)
    gemm_f32out_kernel<<<ggrid, 256, GEMM_SMEM>>>(
        (const __half*)aoh, (const __half*)wph, (const __half*)wpl,
        out, MROWS, DMODEL, DMODEL);
}

// round 12
// speedup vs baseline: 2.1233x; 1.3102x over previous
#include <cuda_runtime.h>
#include <cuda_bf16.h>
#include <cuda_fp16.h>
#include <stdint.h>
#include <math.h>

// Problem constants (fixed): B=2, S=2048, D=2048, H=16
#define BATCH  2
#define SEQ    2048
#define DMODEL 2048
#define NHEAD  16
#define HDIM   128
#define MROWS  (BATCH * SEQ)   // 4096

// ================= scratch (device globals: allocation-free) =================
__device__ __half g_xh [(size_t)MROWS * DMODEL];
__device__ __half g_qh [(size_t)MROWS * DMODEL];
__device__ __half g_kh [(size_t)MROWS * DMODEL];
__device__ __half g_vh [(size_t)MROWS * DMODEL];
__device__ __half g_aoh[(size_t)MROWS * DMODEL];

__device__ __half g_wqh[(size_t)DMODEL * DMODEL];
__device__ __half g_wkh[(size_t)DMODEL * DMODEL];
__device__ __half g_wvh[(size_t)DMODEL * DMODEL];
__device__ __half g_wph[(size_t)DMODEL * DMODEL];
__device__ __half g_wpl[(size_t)DMODEL * DMODEL];

// ================= PTX helpers (baseline features only) ======
__device__ __forceinline__ uint32_t smem_u32(const void* p) {
    uint32_t a;
    asm("{ .reg .u64 t; cvta.to.shared.u64 t, %1; cvt.u32.u64 %0, t; }" : "=r"(a) : "l"(p));
    return a;
}
__device__ __forceinline__ void cp_async16(uint32_t dst, const void* src) {
    asm volatile("cp.async.cg.shared.global [%0], [%1], 16;" :: "r"(dst), "l"(src) : "memory");
}
__device__ __forceinline__ void cp_commit() {
    asm volatile("cp.async.commit_group;" ::: "memory");
}
__device__ __forceinline__ void cp_wait1() {
    asm volatile("cp.async.wait_group 1;" ::: "memory");
}
__device__ __forceinline__ void cp_wait0() {
    asm volatile("cp.async.wait_group 0;" ::: "memory");
}
__device__ __forceinline__ void ldm_x4(uint32_t& r0, uint32_t& r1, uint32_t& r2, uint32_t& r3,
                                       uint32_t addr) {
    asm volatile("ldmatrix.sync.aligned.m8n8.x4.shared.b16 {%0,%1,%2,%3}, [%4];"
                 : "=r"(r0), "=r"(r1), "=r"(r2), "=r"(r3) : "r"(addr));
}
__device__ __forceinline__ void ldm_x4_t(uint32_t& r0, uint32_t& r1, uint32_t& r2, uint32_t& r3,
                                         uint32_t addr) {
    asm volatile("ldmatrix.sync.aligned.m8n8.x4.trans.shared.b16 {%0,%1,%2,%3}, [%4];"
                 : "=r"(r0), "=r"(r1), "=r"(r2), "=r"(r3) : "r"(addr));
}
__device__ __forceinline__ void mma_f16(float* c, const uint32_t* a, uint32_t b0, uint32_t b1) {
    asm volatile("mma.sync.aligned.m16n8k16.row.col.f32.f16.f16.f32 "
                 "{%0,%1,%2,%3}, {%4,%5,%6,%7}, {%8,%9}, {%0,%1,%2,%3};"
                 : "+f"(c[0]), "+f"(c[1]), "+f"(c[2]), "+f"(c[3])
                 : "r"(a[0]), "r"(a[1]), "r"(a[2]), "r"(a[3]), "r"(b0), "r"(b1));
}
__device__ __forceinline__ uint32_t pack_f16x2(float f0, float f1) {
    uint32_t r;
    asm("cvt.rn.f16x2.f32 %0, %1, %2;" : "=r"(r) : "f"(f1), "f"(f0));
    return r;
}

// ================= conversion kernels =================
// fused fp32 -> fp16 single for {x, Wq, Wk, Wv}: blockIdx.y selects tensor
struct CvtSet {
    const float* src[4];
    __half* dst[4];
};
__global__ __launch_bounds__(256) void cvt4_f16_kernel(CvtSet s, int n4)
{
    int i = blockIdx.x * blockDim.x + threadIdx.x;
    if (i >= n4) return;
    int t = blockIdx.y;
    float4 v = ((const float4*)s.src[t])[i];
    uint2 o;
    o.x = pack_f16x2(v.x, v.y);
    o.y = pack_f16x2(v.z, v.w);
    ((uint2*)s.dst[t])[i] = o;
}

// fp32 -> (hi, lo) fp16 split (for Wp only)
__global__ __launch_bounds__(256) void splith_kernel(
    const float* __restrict__ src, __half* __restrict__ hi,
    __half* __restrict__ lo, int n4)
{
    int i = blockIdx.x * blockDim.x + threadIdx.x;
    if (i >= n4) return;
    float4 v = ((const float4*)src)[i];
    __half h0 = __float2half(v.x), h1 = __float2half(v.y);
    __half h2 = __float2half(v.z), h3 = __float2half(v.w);
    uint2 ho, loo;
    ho.x = pack_f16x2(__half2float(h0), __half2float(h1));
    ho.y = pack_f16x2(__half2float(h2), __half2float(h3));
    loo.x = pack_f16x2(v.x - __half2float(h0), v.y - __half2float(h1));
    loo.y = pack_f16x2(v.z - __half2float(h2), v.w - __half2float(h3));
    ((uint2*)hi)[i] = ho;
    ((uint2*)lo)[i] = loo;
}

// ================= fp16 GEMM: C[M,N] = A[M,K] @ B[N,K]^T =====================
// TERMS=1: B single fp16. TERMS=2: B = Bh + Bl.
// CTA tile 128x128, BK=64, 256 threads, double-buffered cp.async.
#define GBK     64
#define TILE_B  (128 * 128)                  // 16 KB per tile

#define T_A  0
#define T_BH (1 * TILE_B)
#define T_BL (2 * TILE_B)

#define QKV_STAGE_B  (2 * TILE_B)
#define QKV_SMEM     (2 * QKV_STAGE_B)       // 65536
#define PRJ_STAGE_B  (3 * TILE_B)
#define PRJ_SMEM     (2 * PRJ_STAGE_B)       // 98304

// MODE 0: fp32 out. MODE 2: fp16 out scaled by mul.
template<int MODE, int TERMS>
__device__ __forceinline__ void gemm_tile_body(
    const __half* __restrict__ A, const __half* __restrict__ Bh,
    const __half* __restrict__ Bl,
    float* __restrict__ C, __half* __restrict__ Ch, float mul, int M, int N, int K,
    int m0, int n0, char* smem)
{
    const int STAGE = (1 + TERMS) * TILE_B;
    const uint32_t sb = smem_u32(smem);
    const int tid = threadIdx.x;
    const int wid = tid >> 5;
    const int l   = tid & 31;
    const int wm  = wid & 3;
    const int wn  = wid >> 2;

    int lrow[4], ldst[4];
    #pragma unroll
    for (int i = 0; i < 4; i++) {
        int idx = tid + i * 256;
        int row = idx >> 3, c16 = idx & 7;
        lrow[i] = row;
        ldst[i] = row * 128 + ((c16 ^ (row & 7)) << 4);
    }

    auto issue_stage = [&](int c, int buf) {
        uint32_t s0 = sb + buf * STAGE;
        #pragma unroll
        for (int i = 0; i < 4; i++) {
            int row = lrow[i];
            int koff = c * GBK + ((tid + i * 256) & 7) * 8;
            cp_async16(s0 + T_A  + ldst[i], A  + (size_t)(m0 + row) * K + koff);
            cp_async16(s0 + T_BH + ldst[i], Bh + (size_t)(n0 + row) * K + koff);
            if (TERMS == 2)
                cp_async16(s0 + T_BL + ldst[i], Bl + (size_t)(n0 + row) * K + koff);
        }
        cp_commit();
    };

    const int a_rowoff = (l & 15);
    const int a_c16off = (l >> 4);
    const int b_rowoff = (l & 7) | ((l & 16) >> 1);
    const int b_c16off = (l >> 3) & 1;

    float acc[2][8][4];
    #pragma unroll
    for (int mi = 0; mi < 2; mi++)
        #pragma unroll
        for (int nj = 0; nj < 8; nj++)
            #pragma unroll
            for (int t = 0; t < 4; t++) acc[mi][nj][t] = 0.f;

    const int nchunks = K / GBK;
    issue_stage(0, 0);
    issue_stage(1, 1);

    for (int c = 0; c < nchunks; c++) {
        const int buf = c & 1;
        if (c < nchunks - 2) cp_wait1(); else cp_wait0();
        __syncthreads();

        const uint32_t s0 = sb + buf * STAGE;
        #pragma unroll
        for (int kk = 0; kk < 4; kk++) {
            uint32_t a[2][4];
            #pragma unroll
            for (int mi = 0; mi < 2; mi++) {
                int row = wm * 32 + mi * 16 + a_rowoff;
                int c16 = kk * 2 + a_c16off;
                uint32_t ad = s0 + T_A + row * 128 + ((c16 ^ (row & 7)) << 4);
                ldm_x4(a[mi][0], a[mi][1], a[mi][2], a[mi][3], ad);
            }
            uint32_t bh[8][2], bl[8][2];
            #pragma unroll
            for (int p = 0; p < 4; p++) {
                int row = wn * 64 + p * 16 + b_rowoff;
                int c16 = kk * 2 + b_c16off;
                uint32_t ad = s0 + row * 128 + ((c16 ^ (row & 7)) << 4);
                ldm_x4(bh[2*p][0], bh[2*p][1], bh[2*p+1][0], bh[2*p+1][1], ad + T_BH);
                if (TERMS == 2)
                    ldm_x4(bl[2*p][0], bl[2*p][1], bl[2*p+1][0], bl[2*p+1][1], ad + T_BL);
            }
            #pragma unroll
            for (int mi = 0; mi < 2; mi++)
                #pragma unroll
                for (int nj = 0; nj < 8; nj++) {
                    mma_f16(acc[mi][nj], a[mi], bh[nj][0], bh[nj][1]);
                    if (TERMS == 2)
                        mma_f16(acc[mi][nj], a[mi], bl[nj][0], bl[nj][1]);
                }
        }
        __syncthreads();
        if (c + 2 < nchunks) issue_stage(c + 2, buf);
    }

    const int er = l >> 2;
    const int ec = (l & 3) * 2;
    #pragma unroll
    for (int mi = 0; mi < 2; mi++) {
        int grow = m0 + wm * 32 + mi * 16 + er;
        #pragma unroll
        for (int nj = 0; nj < 8; nj++) {
            int gcol = n0 + wn * 64 + nj * 8 + ec;
            if (MODE == 0) {
                *(float2*)&C[(size_t)grow * N + gcol] =
                    make_float2(acc[mi][nj][0], acc[mi][nj][1]);
                *(float2*)&C[(size_t)(grow + 8) * N + gcol] =
                    make_float2(acc[mi][nj][2], acc[mi][nj][3]);
            } else {
                *(uint32_t*)&Ch[(size_t)grow * N + gcol] =
                    pack_f16x2(acc[mi][nj][0] * mul, acc[mi][nj][1] * mul);
                *(uint32_t*)&Ch[(size_t)(grow + 8) * N + gcol] =
                    pack_f16x2(acc[mi][nj][2] * mul, acc[mi][nj][3] * mul);
            }
        }
    }
}

// projection: 2-term, fp32 out
__global__ __launch_bounds__(256) void gemm_f32out_kernel(
    const __half* __restrict__ A, const __half* __restrict__ Bh,
    const __half* __restrict__ Bl, float* __restrict__ C, int M, int N, int K)
{
    extern __shared__ char smem[];
    gemm_tile_body<0, 2>(A, Bh, Bl, C, nullptr, 1.0f,
                         M, N, K, blockIdx.y * 128, blockIdx.x * 128, smem);
}

// fused QKV: 1-term, fp16 out
struct QKVSet {
    const __half* b[3];
    __half* ch[3];
    float mul[3];
};
__global__ __launch_bounds__(256) void gemm_qkv_kernel(
    const __half* __restrict__ A, QKVSet s, int M, int N, int K)
{
    extern __shared__ char smem[];
    const int z = blockIdx.z;
    gemm_tile_body<2, 1>(A, s.b[z], nullptr, nullptr, s.ch[z],
                         s.mul[z], M, N, K, blockIdx.y * 128, blockIdx.x * 128, smem);
}

// ============================================================
// Tensor-core flash attention v3 (causal) — fp16, unchanged from round 11.
// ============================================================
#define FT_Q     0
#define FT_STAGE 32768
#define FS_K     0
#define FS_V     16384
#define FLASH_TC_SMEM 98304

__device__ __forceinline__ uint32_t fsw(int row, int c16) {
    return (uint32_t)(row * 256 + ((c16 ^ ((row & 7) << 1)) << 4));
}

__global__ __launch_bounds__(256) void flash_attn_tc_kernel(
    const __half* __restrict__ qh, const __half* __restrict__ kh,
    const __half* __restrict__ vh, __half* __restrict__ oh)
{
    extern __shared__ char fsm[];
    const uint32_t sb = smem_u32(fsm);
    const int tid = threadIdx.x;
    const int wid = tid >> 5;
    const int l   = tid & 31;
    const int qt = gridDim.x - 1 - blockIdx.x;
    const int h  = blockIdx.y;
    const int b  = blockIdx.z;
    const int q0 = qt * 128;

    const size_t gq = ((size_t)b * SEQ + q0) * DMODEL + h * HDIM;
    #pragma unroll
    for (int i = 0; i < 8; i++) {
        int idx = tid + i * 256;
        int row = idx >> 4, c16 = idx & 15;
        cp_async16(sb + FT_Q + fsw(row, c16), qh + gq + (size_t)row * DMODEL + c16 * 8);
    }
    cp_commit();

    auto issue_kv = [&](int kt, int sidx) {
        uint32_t s0 = sb + FT_STAGE + sidx * 32768;
        const size_t gkv = ((size_t)b * SEQ + kt * 64) * DMODEL + h * HDIM;
        #pragma unroll
        for (int i = 0; i < 4; i++) {
            int idx = tid + i * 256;
            int row = idx >> 4, c16 = idx & 15;
            uint32_t off = fsw(row, c16);
            size_t src = gkv + (size_t)row * DMODEL + c16 * 8;
            cp_async16(s0 + FS_K + off, kh + src);
            cp_async16(s0 + FS_V + off, vh + src);
        }
        cp_commit();
    };

    const int r  = l >> 2;
    const int cq = l & 3;
    const int a_rowoff = (l & 15);
    const int a_c16off = (l >> 4);
    const int b_rowoff = (l & 7) | ((l & 16) >> 1);
    const int b_c16off = (l >> 3) & 1;
    const int wrow0 = q0 + wid * 16;

    float m0v = -1e30f, m1v = -1e30f, l0v = 0.f, l1v = 0.f;
    float O[16][4];
    #pragma unroll
    for (int g = 0; g < 16; g++)
        #pragma unroll
        for (int t = 0; t < 4; t++) O[g][t] = 0.f;

    const int nkt = 2 * qt + 2;
    issue_kv(0, 0);

    for (int kt = 0; kt < nkt; kt++) {
        const int sidx = kt & 1;
        if (kt + 1 < nkt) issue_kv(kt + 1, sidx ^ 1);
        if (kt + 1 < nkt) cp_wait1(); else cp_wait0();
        __syncthreads();

        const int col0 = kt * 64;
        if (col0 <= wrow0 + 15) {
            const uint32_t s0 = sb + FT_STAGE + sidx * 32768;

            float s[8][4];
            #pragma unroll
            for (int nj = 0; nj < 8; nj++)
                #pragma unroll
                for (int t = 0; t < 4; t++) s[nj][t] = 0.f;

            #pragma unroll
            for (int j = 0; j < 8; j++) {
                int arow = wid * 16 + a_rowoff;
                uint32_t ah[4];
                ldm_x4(ah[0], ah[1], ah[2], ah[3], sb + FT_Q + fsw(arow, 2 * j + a_c16off));

                uint32_t bh[8][2];
                #pragma unroll
                for (int p = 0; p < 4; p++) {
                    int brow = p * 16 + b_rowoff;
                    uint32_t bad = s0 + FS_K + fsw(brow, 2 * j + b_c16off);
                    ldm_x4(bh[2*p][0], bh[2*p][1], bh[2*p+1][0], bh[2*p+1][1], bad);
                }
                #pragma unroll
                for (int nj = 0; nj < 8; nj++)
                    mma_f16(s[nj], ah, bh[nj][0], bh[nj][1]);
            }

            if (col0 + 63 > wrow0) {
                #pragma unroll
                for (int nj = 0; nj < 8; nj++)
                    #pragma unroll
                    for (int t = 0; t < 4; t++) {
                        int coll = col0 + nj * 8 + 2 * cq + (t & 1);
                        int rowl = wrow0 + r + ((t >> 1) << 3);
                        if (coll > rowl) s[nj][t] = -1e30f;
                    }
            }

            float mx0 = -1e30f, mx1 = -1e30f;
            #pragma unroll
            for (int nj = 0; nj < 8; nj++) {
                mx0 = fmaxf(mx0, fmaxf(s[nj][0], s[nj][1]));
                mx1 = fmaxf(mx1, fmaxf(s[nj][2], s[nj][3]));
            }
            mx0 = fmaxf(mx0, __shfl_xor_sync(0xffffffffu, mx0, 1));
            mx0 = fmaxf(mx0, __shfl_xor_sync(0xffffffffu, mx0, 2));
            mx1 = fmaxf(mx1, __shfl_xor_sync(0xffffffffu, mx1, 1));
            mx1 = fmaxf(mx1, __shfl_xor_sync(0xffffffffu, mx1, 2));

            float mn0 = fmaxf(m0v, mx0), mn1 = fmaxf(m1v, mx1);
            float al0 = __expf(m0v - mn0), al1 = __expf(m1v - mn1);
            m0v = mn0; m1v = mn1;

            #pragma unroll
            for (int g = 0; g < 16; g++) {
                O[g][0] *= al0; O[g][1] *= al0;
                O[g][2] *= al1; O[g][3] *= al1;
            }

            float rs0 = 0.f, rs1 = 0.f;
            #pragma unroll
            for (int nj = 0; nj < 8; nj++) {
                s[nj][0] = __expf(s[nj][0] - mn0);
                s[nj][1] = __expf(s[nj][1] - mn0);
                s[nj][2] = __expf(s[nj][2] - mn1);
                s[nj][3] = __expf(s[nj][3] - mn1);
                rs0 += s[nj][0] + s[nj][1];
                rs1 += s[nj][2] + s[nj][3];
            }
            rs0 += __shfl_xor_sync(0xffffffffu, rs0, 1);
            rs0 += __shfl_xor_sync(0xffffffffu, rs0, 2);
            rs1 += __shfl_xor_sync(0xffffffffu, rs1, 1);
            rs1 += __shfl_xor_sync(0xffffffffu, rs1, 2);
            l0v = l0v * al0 + rs0;
            l1v = l1v * al1 + rs1;

            #pragma unroll
            for (int j = 0; j < 4; j++) {
                uint32_t pa[4];
                pa[0] = pack_f16x2(s[2*j][0],   s[2*j][1]);
                pa[1] = pack_f16x2(s[2*j][2],   s[2*j][3]);
                pa[2] = pack_f16x2(s[2*j+1][0], s[2*j+1][1]);
                pa[3] = pack_f16x2(s[2*j+1][2], s[2*j+1][3]);
                #pragma unroll
                for (int g = 0; g < 8; g++) {
                    int vrow = j * 16 + (l & 15);
                    uint32_t vad = s0 + FS_V + fsw(vrow, 2 * g + (l >> 4));
                    uint32_t v0, v1, v2, v3;
                    ldm_x4_t(v0, v1, v2, v3, vad);
                    mma_f16(O[2*g],     pa, v0, v1);
                    mma_f16(O[2*g + 1], pa, v2, v3);
                }
            }
        }
        __syncthreads();
    }

    const float i0 = 1.0f / l0v;
    const float i1 = 1.0f / l1v;
    const size_t obase = ((size_t)b * SEQ + q0 + wid * 16 + r) * DMODEL + h * HDIM;
    #pragma unroll
    for (int g = 0; g < 16; g++) {
        int col = g * 8 + 2 * cq;
        *(uint32_t*)&oh[obase + col] = pack_f16x2(O[g][0] * i0, O[g][1] * i0);
        *(uint32_t*)&oh[obase + (size_t)8 * DMODEL + col] =
            pack_f16x2(O[g][2] * i1, O[g][3] * i1);
    }
}

// ============================================================
// launcher
// ============================================================
extern "C" void kernel_launch(void* const* d_in, const int* in_sizes, int n_in,
                              void* d_out, int out_size)
{
    const float* x  = (const float*)d_in[0];
    const float* Wq = (const float*)d_in[1];
    const float* Wk = (const float*)d_in[2];
    const float* Wv = (const float*)d_in[3];
    const float* Wp = (const float*)d_in[4];
    float* out = (float*)d_out;

    void *xh, *qh, *kh, *vh, *aoh;
    cudaGetSymbolAddress(&xh,  g_xh);
    cudaGetSymbolAddress(&qh,  g_qh);
    cudaGetSymbolAddress(&kh,  g_kh);
    cudaGetSymbolAddress(&vh,  g_vh);
    cudaGetSymbolAddress(&aoh, g_aoh);

    void *wqh, *wkh, *wvh, *wph, *wpl;
    cudaGetSymbolAddress(&wqh, g_wqh);
    cudaGetSymbolAddress(&wkh, g_wkh);
    cudaGetSymbolAddress(&wvh, g_wvh);
    cudaGetSymbolAddress(&wph, g_wph);
    cudaGetSymbolAddress(&wpl, g_wpl);

    cudaFuncSetAttribute(flash_attn_tc_kernel,
                         cudaFuncAttributeMaxDynamicSharedMemorySize, FLASH_TC_SMEM);
    cudaFuncSetAttribute(gemm_f32out_kernel,
                         cudaFuncAttributeMaxDynamicSharedMemorySize, PRJ_SMEM);
    cudaFuncSetAttribute(gemm_qkv_kernel,
                         cudaFuncAttributeMaxDynamicSharedMemorySize, QKV_SMEM);

    const int nx4 = (MROWS * DMODEL) / 4;
    const int nw4 = (DMODEL * DMODEL) / 4;

    // fused conversion of x, Wq, Wk, Wv to fp16; Wp split hi/lo
    {
        CvtSet cs;
        cs.src[0] = x;  cs.dst[0] = (__half*)xh;
        cs.src[1] = Wq; cs.dst[1] = (__half*)wqh;
        cs.src[2] = Wk; cs.dst[2] = (__half*)wkh;
        cs.src[3] = Wv; cs.dst[3] = (__half*)wvh;
        dim3 cg((nx4 + 255) / 256, 4);   // n4 max = nx4 (x is largest: 2M float4)
        // note: weight tensors are nw4 = 1M float4; guard inside kernel uses per-tensor n4
        // -> launch separately sized: x uses nx4, weights use nw4. Use two launches.
        CvtSet cx; cx.src[0] = x; cx.dst[0] = (__half*)xh;
        cx.src[1] = x; cx.dst[1] = (__half*)xh;   // unused lanes
        (void)cx;
        // simpler: one launch for x, one fused for the 3 QKV weights
        dim3 g1((nx4 + 255) / 256, 1);
        CvtSet sx; sx.src[0] = x; sx.dst[0] = (__half*)xh;
        cvt4_f16_kernel<<<g1, 256>>>(sx, nx4);
        CvtSet sw;
        sw.src[0] = Wq; sw.dst[0] = (__half*)wqh;
        sw.src[1] = Wk; sw.dst[1] = (__half*)wkh;
        sw.src[2] = Wv; sw.dst[2] = (__half*)wvh;
        sw.src[3] = Wq; sw.dst[3] = (__half*)wqh;  // dup slot (harmless rewrite)
        dim3 g3((nw4 + 255) / 256, 3);
        cvt4_f16_kernel<<<g3, 256>>>(sw, nw4);
        (void)cg;
    }
    splith_kernel<<<(nw4 + 255) / 256, 256>>>(Wp, (__half*)wph, (__half*)wpl, nw4);

    const float scale = 0.08838834764831845f;  // 1/sqrt(128), folded into Q

    {
        QKVSet qs;
        qs.b[0] = (const __half*)wqh; qs.ch[0] = (__half*)qh; qs.mul[0] = scale;
        qs.b[1] = (const __half*)wkh; qs.ch[1] = (__half*)kh; qs.mul[1] = 1.0f;
        qs.b[2] = (const __half*)wvh; qs.ch[2] = (__half*)vh; qs.mul[2] = 1.0f;
        dim3 qg(DMODEL / 128, MROWS / 128, 3);   // (16, 32, 3)
        gemm_qkv_kernel<<<qg, 256, QKV_SMEM>>>(
            (const __half*)xh, qs, MROWS, DMODEL, DMODEL);
    }

    dim3 fgrid(SEQ / 128, NHEAD, BATCH);     // (16, 16, 2)
    flash_attn_tc_kernel<<<fgrid, 256, FLASH_TC_SMEM>>>(
        (const __half*)qh, (const __half*)kh, (const __half*)vh, (__half*)aoh);

    dim3 ggrid(DMODEL / 128, MROWS / 128);   // (16, 32)
    gemm_f32out_kernel<<<ggrid, 256, PRJ_SMEM>>>(
        (const __half*)aoh, (const __half*)wph, (const __half*)wpl,
        out, MROWS, DMODEL, DMODEL);
}

// round 13
// speedup vs baseline: 2.3936x; 1.1273x over previous
#include <cuda_runtime.h>
#include <cuda_bf16.h>
#include <cuda_fp16.h>
#include <stdint.h>
#include <math.h>

// Problem constants (fixed): B=2, S=2048, D=2048, H=16
#define BATCH  2
#define SEQ    2048
#define DMODEL 2048
#define NHEAD  16
#define HDIM   128
#define MROWS  (BATCH * SEQ)   // 4096

// ================= scratch (device globals: allocation-free) =================
__device__ __half g_xh [(size_t)MROWS * DMODEL];
__device__ __half g_qh [(size_t)MROWS * DMODEL];
__device__ __half g_kh [(size_t)MROWS * DMODEL];
__device__ __half g_vh [(size_t)MROWS * DMODEL];
__device__ __half g_aoh[(size_t)MROWS * DMODEL];

__device__ __half g_wqh[(size_t)DMODEL * DMODEL];
__device__ __half g_wkh[(size_t)DMODEL * DMODEL];
__device__ __half g_wvh[(size_t)DMODEL * DMODEL];
__device__ __half g_wph[(size_t)DMODEL * DMODEL];

// ================= PTX helpers (baseline features only) ======
__device__ __forceinline__ uint32_t smem_u32(const void* p) {
    uint32_t a;
    asm("{ .reg .u64 t; cvta.to.shared.u64 t, %1; cvt.u32.u64 %0, t; }" : "=r"(a) : "l"(p));
    return a;
}
__device__ __forceinline__ void cp_async16(uint32_t dst, const void* src) {
    asm volatile("cp.async.cg.shared.global [%0], [%1], 16;" :: "r"(dst), "l"(src) : "memory");
}
__device__ __forceinline__ void cp_commit() {
    asm volatile("cp.async.commit_group;" ::: "memory");
}
__device__ __forceinline__ void cp_wait1() {
    asm volatile("cp.async.wait_group 1;" ::: "memory");
}
__device__ __forceinline__ void cp_wait0() {
    asm volatile("cp.async.wait_group 0;" ::: "memory");
}
__device__ __forceinline__ void ldm_x4(uint32_t& r0, uint32_t& r1, uint32_t& r2, uint32_t& r3,
                                       uint32_t addr) {
    asm volatile("ldmatrix.sync.aligned.m8n8.x4.shared.b16 {%0,%1,%2,%3}, [%4];"
                 : "=r"(r0), "=r"(r1), "=r"(r2), "=r"(r3) : "r"(addr));
}
__device__ __forceinline__ void ldm_x4_t(uint32_t& r0, uint32_t& r1, uint32_t& r2, uint32_t& r3,
                                         uint32_t addr) {
    asm volatile("ldmatrix.sync.aligned.m8n8.x4.trans.shared.b16 {%0,%1,%2,%3}, [%4];"
                 : "=r"(r0), "=r"(r1), "=r"(r2), "=r"(r3) : "r"(addr));
}
__device__ __forceinline__ void mma_f16(float* c, const uint32_t* a, uint32_t b0, uint32_t b1) {
    asm volatile("mma.sync.aligned.m16n8k16.row.col.f32.f16.f16.f32 "
                 "{%0,%1,%2,%3}, {%4,%5,%6,%7}, {%8,%9}, {%0,%1,%2,%3};"
                 : "+f"(c[0]), "+f"(c[1]), "+f"(c[2]), "+f"(c[3])
                 : "r"(a[0]), "r"(a[1]), "r"(a[2]), "r"(a[3]), "r"(b0), "r"(b1));
}
__device__ __forceinline__ uint32_t pack_f16x2(float f0, float f1) {
    uint32_t r;
    asm("cvt.rn.f16x2.f32 %0, %1, %2;" : "=r"(r) : "f"(f1), "f"(f0));
    return r;
}

// ================= conversion kernel =================
// fused fp32 -> fp16; blockIdx.y selects tensor
struct CvtSet {
    const float* src[4];
    __half* dst[4];
};
__global__ __launch_bounds__(256) void cvt4_f16_kernel(CvtSet s, int n4)
{
    int i = blockIdx.x * blockDim.x + threadIdx.x;
    if (i >= n4) return;
    int t = blockIdx.y;
    float4 v = ((const float4*)s.src[t])[i];
    uint2 o;
    o.x = pack_f16x2(v.x, v.y);
    o.y = pack_f16x2(v.z, v.w);
    ((uint2*)s.dst[t])[i] = o;
}

// ================= fp16 GEMM: C[M,N] = A[M,K] @ B[N,K]^T =====================
// Single-term fp16. CTA tile 128x128, BK=64, 256 threads, double-buffered.
#define GBK     64
#define TILE_B  (128 * 128)                  // 16 KB per tile

#define T_A  0
#define T_B  (1 * TILE_B)

#define GEMM_STAGE_B (2 * TILE_B)
#define GEMM_SMEM    (2 * GEMM_STAGE_B)      // 65536

// MODE 0: fp32 out. MODE 2: fp16 out scaled by mul.
template<int MODE>
__device__ __forceinline__ void gemm_tile_body(
    const __half* __restrict__ A, const __half* __restrict__ B,
    float* __restrict__ C, __half* __restrict__ Ch, float mul, int M, int N, int K,
    int m0, int n0, char* smem)
{
    const uint32_t sb = smem_u32(smem);
    const int tid = threadIdx.x;
    const int wid = tid >> 5;
    const int l   = tid & 31;
    const int wm  = wid & 3;
    const int wn  = wid >> 2;

    int lrow[4], ldst[4];
    #pragma unroll
    for (int i = 0; i < 4; i++) {
        int idx = tid + i * 256;
        int row = idx >> 3, c16 = idx & 7;
        lrow[i] = row;
        ldst[i] = row * 128 + ((c16 ^ (row & 7)) << 4);
    }

    auto issue_stage = [&](int c, int buf) {
        uint32_t s0 = sb + buf * GEMM_STAGE_B;
        #pragma unroll
        for (int i = 0; i < 4; i++) {
            int row = lrow[i];
            int koff = c * GBK + ((tid + i * 256) & 7) * 8;
            cp_async16(s0 + T_A + ldst[i], A + (size_t)(m0 + row) * K + koff);
            cp_async16(s0 + T_B + ldst[i], B + (size_t)(n0 + row) * K + koff);
        }
        cp_commit();
    };

    const int a_rowoff = (l & 15);
    const int a_c16off = (l >> 4);
    const int b_rowoff = (l & 7) | ((l & 16) >> 1);
    const int b_c16off = (l >> 3) & 1;

    float acc[2][8][4];
    #pragma unroll
    for (int mi = 0; mi < 2; mi++)
        #pragma unroll
        for (int nj = 0; nj < 8; nj++)
            #pragma unroll
            for (int t = 0; t < 4; t++) acc[mi][nj][t] = 0.f;

    const int nchunks = K / GBK;
    issue_stage(0, 0);
    issue_stage(1, 1);

    for (int c = 0; c < nchunks; c++) {
        const int buf = c & 1;
        if (c < nchunks - 2) cp_wait1(); else cp_wait0();
        __syncthreads();

        const uint32_t s0 = sb + buf * GEMM_STAGE_B;
        #pragma unroll
        for (int kk = 0; kk < 4; kk++) {
            uint32_t a[2][4];
            #pragma unroll
            for (int mi = 0; mi < 2; mi++) {
                int row = wm * 32 + mi * 16 + a_rowoff;
                int c16 = kk * 2 + a_c16off;
                uint32_t ad = s0 + T_A + row * 128 + ((c16 ^ (row & 7)) << 4);
                ldm_x4(a[mi][0], a[mi][1], a[mi][2], a[mi][3], ad);
            }
            uint32_t bh[8][2];
            #pragma unroll
            for (int p = 0; p < 4; p++) {
                int row = wn * 64 + p * 16 + b_rowoff;
                int c16 = kk * 2 + b_c16off;
                uint32_t ad = s0 + T_B + row * 128 + ((c16 ^ (row & 7)) << 4);
                ldm_x4(bh[2*p][0], bh[2*p][1], bh[2*p+1][0], bh[2*p+1][1], ad);
            }
            #pragma unroll
            for (int mi = 0; mi < 2; mi++)
                #pragma unroll
                for (int nj = 0; nj < 8; nj++)
                    mma_f16(acc[mi][nj], a[mi], bh[nj][0], bh[nj][1]);
        }
        __syncthreads();
        if (c + 2 < nchunks) issue_stage(c + 2, buf);
    }

    const int er = l >> 2;
    const int ec = (l & 3) * 2;
    #pragma unroll
    for (int mi = 0; mi < 2; mi++) {
        int grow = m0 + wm * 32 + mi * 16 + er;
        #pragma unroll
        for (int nj = 0; nj < 8; nj++) {
            int gcol = n0 + wn * 64 + nj * 8 + ec;
            if (MODE == 0) {
                *(float2*)&C[(size_t)grow * N + gcol] =
                    make_float2(acc[mi][nj][0], acc[mi][nj][1]);
                *(float2*)&C[(size_t)(grow + 8) * N + gcol] =
                    make_float2(acc[mi][nj][2], acc[mi][nj][3]);
            } else {
                *(uint32_t*)&Ch[(size_t)grow * N + gcol] =
                    pack_f16x2(acc[mi][nj][0] * mul, acc[mi][nj][1] * mul);
                *(uint32_t*)&Ch[(size_t)(grow + 8) * N + gcol] =
                    pack_f16x2(acc[mi][nj][2] * mul, acc[mi][nj][3] * mul);
            }
        }
    }
}

// projection: 1-term, fp32 out
__global__ __launch_bounds__(256) void gemm_f32out_kernel(
    const __half* __restrict__ A, const __half* __restrict__ B,
    float* __restrict__ C, int M, int N, int K)
{
    extern __shared__ char smem[];
    gemm_tile_body<0>(A, B, C, nullptr, 1.0f,
                      M, N, K, blockIdx.y * 128, blockIdx.x * 128, smem);
}

// fused QKV: 1-term, fp16 out
struct QKVSet {
    const __half* b[3];
    __half* ch[3];
    float mul[3];
};
__global__ __launch_bounds__(256) void gemm_qkv_kernel(
    const __half* __restrict__ A, QKVSet s, int M, int N, int K)
{
    extern __shared__ char smem[];
    const int z = blockIdx.z;
    gemm_tile_body<2>(A, s.b[z], nullptr, s.ch[z],
                      s.mul[z], M, N, K, blockIdx.y * 128, blockIdx.x * 128, smem);
}

// ============================================================
// Tensor-core flash attention v3 (causal) — fp16.
// Block: 256 threads (8 warps); BQ=128, BKV=64, hd=128.
// __launch_bounds__(256, 2): cap regs at 128 for 2 CTAs/SM.
// smem: Q 32KB + 2 stages x 32KB = 96 KB (2 CTAs = 192 KB).
// ============================================================
#define FT_Q     0
#define FT_STAGE 32768
#define FS_K     0
#define FS_V     16384
#define FLASH_TC_SMEM 98304

__device__ __forceinline__ uint32_t fsw(int row, int c16) {
    return (uint32_t)(row * 256 + ((c16 ^ ((row & 7) << 1)) << 4));
}

__global__ __launch_bounds__(256, 2) void flash_attn_tc_kernel(
    const __half* __restrict__ qh, const __half* __restrict__ kh,
    const __half* __restrict__ vh, __half* __restrict__ oh)
{
    extern __shared__ char fsm[];
    const uint32_t sb = smem_u32(fsm);
    const int tid = threadIdx.x;
    const int wid = tid >> 5;
    const int l   = tid & 31;
    const int qt = gridDim.x - 1 - blockIdx.x;   // longest-first scheduling
    const int h  = blockIdx.y;
    const int b  = blockIdx.z;
    const int q0 = qt * 128;

    const size_t gq = ((size_t)b * SEQ + q0) * DMODEL + h * HDIM;
    #pragma unroll
    for (int i = 0; i < 8; i++) {
        int idx = tid + i * 256;
        int row = idx >> 4, c16 = idx & 15;
        cp_async16(sb + FT_Q + fsw(row, c16), qh + gq + (size_t)row * DMODEL + c16 * 8);
    }
    cp_commit();

    auto issue_kv = [&](int kt, int sidx) {
        uint32_t s0 = sb + FT_STAGE + sidx * 32768;
        const size_t gkv = ((size_t)b * SEQ + kt * 64) * DMODEL + h * HDIM;
        #pragma unroll
        for (int i = 0; i < 4; i++) {
            int idx = tid + i * 256;
            int row = idx >> 4, c16 = idx & 15;
            uint32_t off = fsw(row, c16);
            size_t src = gkv + (size_t)row * DMODEL + c16 * 8;
            cp_async16(s0 + FS_K + off, kh + src);
            cp_async16(s0 + FS_V + off, vh + src);
        }
        cp_commit();
    };

    const int r  = l >> 2;
    const int cq = l & 3;
    const int a_rowoff = (l & 15);
    const int a_c16off = (l >> 4);
    const int b_rowoff = (l & 7) | ((l & 16) >> 1);
    const int b_c16off = (l >> 3) & 1;
    const int wrow0 = q0 + wid * 16;

    float m0v = -1e30f, m1v = -1e30f, l0v = 0.f, l1v = 0.f;
    float O[16][4];
    #pragma unroll
    for (int g = 0; g < 16; g++)
        #pragma unroll
        for (int t = 0; t < 4; t++) O[g][t] = 0.f;

    const int nkt = 2 * qt + 2;
    issue_kv(0, 0);

    for (int kt = 0; kt < nkt; kt++) {
        const int sidx = kt & 1;
        if (kt + 1 < nkt) issue_kv(kt + 1, sidx ^ 1);
        if (kt + 1 < nkt) cp_wait1(); else cp_wait0();
        __syncthreads();

        const int col0 = kt * 64;
        if (col0 <= wrow0 + 15) {        // warp-level causal skip
            const uint32_t s0 = sb + FT_STAGE + sidx * 32768;

            float s[8][4];
            #pragma unroll
            for (int nj = 0; nj < 8; nj++)
                #pragma unroll
                for (int t = 0; t < 4; t++) s[nj][t] = 0.f;

            #pragma unroll
            for (int j = 0; j < 8; j++) {
                int arow = wid * 16 + a_rowoff;
                uint32_t ah[4];
                ldm_x4(ah[0], ah[1], ah[2], ah[3], sb + FT_Q + fsw(arow, 2 * j + a_c16off));

                uint32_t bh[8][2];
                #pragma unroll
                for (int p = 0; p < 4; p++) {
                    int brow = p * 16 + b_rowoff;
                    uint32_t bad = s0 + FS_K + fsw(brow, 2 * j + b_c16off);
                    ldm_x4(bh[2*p][0], bh[2*p][1], bh[2*p+1][0], bh[2*p+1][1], bad);
                }
                #pragma unroll
                for (int nj = 0; nj < 8; nj++)
                    mma_f16(s[nj], ah, bh[nj][0], bh[nj][1]);
            }

            if (col0 + 63 > wrow0) {
                #pragma unroll
                for (int nj = 0; nj < 8; nj++)
                    #pragma unroll
                    for (int t = 0; t < 4; t++) {
                        int coll = col0 + nj * 8 + 2 * cq + (t & 1);
                        int rowl = wrow0 + r + ((t >> 1) << 3);
                        if (coll > rowl) s[nj][t] = -1e30f;
                    }
            }

            float mx0 = -1e30f, mx1 = -1e30f;
            #pragma unroll
            for (int nj = 0; nj < 8; nj++) {
                mx0 = fmaxf(mx0, fmaxf(s[nj][0], s[nj][1]));
                mx1 = fmaxf(mx1, fmaxf(s[nj][2], s[nj][3]));
            }
            mx0 = fmaxf(mx0, __shfl_xor_sync(0xffffffffu, mx0, 1));
            mx0 = fmaxf(mx0, __shfl_xor_sync(0xffffffffu, mx0, 2));
            mx1 = fmaxf(mx1, __shfl_xor_sync(0xffffffffu, mx1, 1));
            mx1 = fmaxf(mx1, __shfl_xor_sync(0xffffffffu, mx1, 2));

            float mn0 = fmaxf(m0v, mx0), mn1 = fmaxf(m1v, mx1);
            float al0 = __expf(m0v - mn0), al1 = __expf(m1v - mn1);
            m0v = mn0; m1v = mn1;

            #pragma unroll
            for (int g = 0; g < 16; g++) {
                O[g][0] *= al0; O[g][1] *= al0;
                O[g][2] *= al1; O[g][3] *= al1;
            }

            float rs0 = 0.f, rs1 = 0.f;
            #pragma unroll
            for (int nj = 0; nj < 8; nj++) {
                s[nj][0] = __expf(s[nj][0] - mn0);
                s[nj][1] = __expf(s[nj][1] - mn0);
                s[nj][2] = __expf(s[nj][2] - mn1);
                s[nj][3] = __expf(s[nj][3] - mn1);
                rs0 += s[nj][0] + s[nj][1];
                rs1 += s[nj][2] + s[nj][3];
            }
            rs0 += __shfl_xor_sync(0xffffffffu, rs0, 1);
            rs0 += __shfl_xor_sync(0xffffffffu, rs0, 2);
            rs1 += __shfl_xor_sync(0xffffffffu, rs1, 1);
            rs1 += __shfl_xor_sync(0xffffffffu, rs1, 2);
            l0v = l0v * al0 + rs0;
            l1v = l1v * al1 + rs1;

            #pragma unroll
            for (int j = 0; j < 4; j++) {
                uint32_t pa[4];
                pa[0] = pack_f16x2(s[2*j][0],   s[2*j][1]);
                pa[1] = pack_f16x2(s[2*j][2],   s[2*j][3]);
                pa[2] = pack_f16x2(s[2*j+1][0], s[2*j+1][1]);
                pa[3] = pack_f16x2(s[2*j+1][2], s[2*j+1][3]);
                #pragma unroll
                for (int g = 0; g < 8; g++) {
                    int vrow = j * 16 + (l & 15);
                    uint32_t vad = s0 + FS_V + fsw(vrow, 2 * g + (l >> 4));
                    uint32_t v0, v1, v2, v3;
                    ldm_x4_t(v0, v1, v2, v3, vad);
                    mma_f16(O[2*g],     pa, v0, v1);
                    mma_f16(O[2*g + 1], pa, v2, v3);
                }
            }
        }
        __syncthreads();
    }

    const float i0 = 1.0f / l0v;
    const float i1 = 1.0f / l1v;
    const size_t obase = ((size_t)b * SEQ + q0 + wid * 16 + r) * DMODEL + h * HDIM;
    #pragma unroll
    for (int g = 0; g < 16; g++) {
        int col = g * 8 + 2 * cq;
        *(uint32_t*)&oh[obase + col] = pack_f16x2(O[g][0] * i0, O[g][1] * i0);
        *(uint32_t*)&oh[obase + (size_t)8 * DMODEL + col] =
            pack_f16x2(O[g][2] * i1, O[g][3] * i1);
    }
}

// ============================================================
// launcher
// ============================================================
extern "C" void kernel_launch(void* const* d_in, const int* in_sizes, int n_in,
                              void* d_out, int out_size)
{
    const float* x  = (const float*)d_in[0];
    const float* Wq = (const float*)d_in[1];
    const float* Wk = (const float*)d_in[2];
    const float* Wv = (const float*)d_in[3];
    const float* Wp = (const float*)d_in[4];
    float* out = (float*)d_out;

    void *xh, *qh, *kh, *vh, *aoh;
    cudaGetSymbolAddress(&xh,  g_xh);
    cudaGetSymbolAddress(&qh,  g_qh);
    cudaGetSymbolAddress(&kh,  g_kh);
    cudaGetSymbolAddress(&vh,  g_vh);
    cudaGetSymbolAddress(&aoh, g_aoh);

    void *wqh, *wkh, *wvh, *wph;
    cudaGetSymbolAddress(&wqh, g_wqh);
    cudaGetSymbolAddress(&wkh, g_wkh);
    cudaGetSymbolAddress(&wvh, g_wvh);
    cudaGetSymbolAddress(&wph, g_wph);

    cudaFuncSetAttribute(flash_attn_tc_kernel,
                         cudaFuncAttributeMaxDynamicSharedMemorySize, FLASH_TC_SMEM);
    cudaFuncSetAttribute(gemm_f32out_kernel,
                         cudaFuncAttributeMaxDynamicSharedMemorySize, GEMM_SMEM);
    cudaFuncSetAttribute(gemm_qkv_kernel,
                         cudaFuncAttributeMaxDynamicSharedMemorySize, GEMM_SMEM);

    const int nx4 = (MROWS * DMODEL) / 4;
    const int nw4 = (DMODEL * DMODEL) / 4;

    // conversions: x alone (2M float4), then 4 weights fused (1M float4 each)
    {
        CvtSet sx;
        sx.src[0] = x; sx.dst[0] = (__half*)xh;
        dim3 g1((nx4 + 255) / 256, 1);
        cvt4_f16_kernel<<<g1, 256>>>(sx, nx4);

        CvtSet sw;
        sw.src[0] = Wq; sw.dst[0] = (__half*)wqh;
        sw.src[1] = Wk; sw.dst[1] = (__half*)wkh;
        sw.src[2] = Wv; sw.dst[2] = (__half*)wvh;
        sw.src[3] = Wp; sw.dst[3] = (__half*)wph;
        dim3 g4((nw4 + 255) / 256, 4);
        cvt4_f16_kernel<<<g4, 256>>>(sw, nw4);
    }

    const float scale = 0.08838834764831845f;  // 1/sqrt(128), folded into Q

    {
        QKVSet qs;
        qs.b[0] = (const __half*)wqh; qs.ch[0] = (__half*)qh; qs.mul[0] = scale;
        qs.b[1] = (const __half*)wkh; qs.ch[1] = (__half*)kh; qs.mul[1] = 1.0f;
        qs.b[2] = (const __half*)wvh; qs.ch[2] = (__half*)vh; qs.mul[2] = 1.0f;
        dim3 qg(DMODEL / 128, MROWS / 128, 3);   // (16, 32, 3)
        gemm_qkv_kernel<<<qg, 256, GEMM_SMEM>>>(
            (const __half*)xh, qs, MROWS, DMODEL, DMODEL);
    }

    dim3 fgrid(SEQ / 128, NHEAD, BATCH);     // (16, 16, 2)
    flash_attn_tc_kernel<<<fgrid, 256, FLASH_TC_SMEM>>>(
        (const __half*)qh, (const __half*)kh, (const __half*)vh, (__half*)aoh);

    dim3 ggrid(DMODEL / 128, MROWS / 128);   // (16, 32)
    gemm_f32out_kernel<<<ggrid, 256, GEMM_SMEM>>>(
        (const __half*)aoh, (const __half*)wph,
        out, MROWS, DMODEL, DMODEL);
}